// round 3
// baseline (speedup 1.0000x reference)
#include <cuda_runtime.h>
#include <cuda_bf16.h>
#include <cstdint>

#define BDIM 4096
#define KMOD 4
#define DIN  1024
#define HDIM 1024
#define CTXD 256
#define RHD  64
#define KDIM 4096  /* KMOD*DIN : concatenated reduction dim */

// ---------------- scratch (device globals: no runtime allocation) ----------------
__device__ float          g_c [BDIM * KMOD];                       // gate coeff c[b,k]
__device__ __nv_bfloat16  g_Ah[(size_t)BDIM * KDIM];               // hi(c*x)  [B][K]
__device__ __nv_bfloat16  g_Al[(size_t)BDIM * KDIM];               // lo(c*x)
__device__ __nv_bfloat16  g_Wh[(size_t)KDIM * HDIM];               // hi(W_enc) [K][H]
__device__ __nv_bfloat16  g_Wl[(size_t)KDIM * HDIM];               // lo(W_enc)

// ---------------- router: Linear->LN->ReLU->Linear->ReLU->Linear->gate ----------------
__global__ void router_kernel(const float* __restrict__ context,
                              const float* __restrict__ gumbel,
                              const float* __restrict__ W1, const float* __restrict__ b1,
                              const float* __restrict__ gln, const float* __restrict__ bln,
                              const float* __restrict__ W2, const float* __restrict__ b2,
                              const float* __restrict__ W3, const float* __restrict__ b3,
                              const float* __restrict__ prior,
                              const float* __restrict__ fusion_w)
{
    __shared__ float ctx_s[8][CTXD];
    __shared__ float h1_s[8][RHD];
    __shared__ float h2_s[8][RHD / 2];
    const int warp = threadIdx.x >> 5, lane = threadIdx.x & 31;
    const int b = blockIdx.x * 8 + warp;

    const float* crow = context + (size_t)b * CTXD;
    for (int i = lane; i < CTXD; i += 32) ctx_s[warp][i] = crow[i];
    __syncwarp();

    float h[2];
#pragma unroll
    for (int jj = 0; jj < 2; jj++) {
        const int j = lane + jj * 32;
        float acc = b1[j];
        for (int i = 0; i < CTXD; i++) acc = fmaf(ctx_s[warp][i], W1[i * RHD + j], acc);
        h[jj] = acc;
    }
    float s  = h[0] + h[1];
    float sq = h[0] * h[0] + h[1] * h[1];
#pragma unroll
    for (int o = 16; o; o >>= 1) {
        s  += __shfl_xor_sync(0xffffffffu, s,  o);
        sq += __shfl_xor_sync(0xffffffffu, sq, o);
    }
    const float mu   = s * (1.0f / RHD);
    const float var  = sq * (1.0f / RHD) - mu * mu;
    const float rstd = rsqrtf(var + 1e-5f);
#pragma unroll
    for (int jj = 0; jj < 2; jj++) {
        const int j = lane + jj * 32;
        const float v = (h[jj] - mu) * rstd * gln[j] + bln[j];
        h1_s[warp][j] = fmaxf(v, 0.0f);
    }
    __syncwarp();
    float acc2 = b2[lane];
    for (int i = 0; i < RHD; i++) acc2 = fmaf(h1_s[warp][i], W2[i * (RHD / 2) + lane], acc2);
    h2_s[warp][lane] = fmaxf(acc2, 0.0f);
    __syncwarp();

    float logit = 0.0f;
    if (lane < KMOD) {
        logit = b3[lane] + prior[lane];
        for (int i = 0; i < RHD / 2; i++) logit = fmaf(h2_s[warp][i], W3[i * KMOD + lane], logit);
    }
    float lg[4];
#pragma unroll
    for (int k = 0; k < 4; k++) lg[k] = __shfl_sync(0xffffffffu, logit, k);

    if (lane == 0) {
        float fw[4], m = -1e30f;
#pragma unroll
        for (int k = 0; k < 4; k++) { fw[k] = fusion_w[k]; m = fmaxf(m, fw[k]); }
        float se = 0.0f;
#pragma unroll
        for (int k = 0; k < 4; k++) { fw[k] = expf(fw[k] - m); se += fw[k]; }
        const float inv = 1.0f / se;
        int i1 = 0;
#pragma unroll
        for (int k = 1; k < 4; k++) if (lg[k] > lg[i1]) i1 = k;
        int i2 = (i1 == 0) ? 1 : 0;
#pragma unroll
        for (int k = 0; k < 4; k++) if (k != i1 && lg[k] > lg[i2]) i2 = k;
#pragma unroll
        for (int k = 0; k < 4; k++) {
            const float soft = 1.0f / (1.0f + expf(-(lg[k] + gumbel[b * KMOD + k])));
            const float mask = (k == i1 || k == i2) ? fmaxf(soft, 1.0f) : soft;
            const float cc   = (mask > 0.5f) ? (fw[k] * inv) * mask : 0.0f;
            g_c[b * KMOD + k] = cc;
        }
    }
}

// ---------------- hi/lo split of W_enc (elementwise; layout [k*DIN+d][h]) ----------------
__global__ void split_w_kernel(const float* __restrict__ W)
{
    const size_t t = (size_t)blockIdx.x * blockDim.x + threadIdx.x;   // over KDIM*HDIM/4
    const float4 v = reinterpret_cast<const float4*>(W)[t];
    __nv_bfloat16 h0 = __float2bfloat16(v.x), h1 = __float2bfloat16(v.y);
    __nv_bfloat16 h2 = __float2bfloat16(v.z), h3 = __float2bfloat16(v.w);
    __nv_bfloat16 l0 = __float2bfloat16(v.x - __bfloat162float(h0));
    __nv_bfloat16 l1 = __float2bfloat16(v.y - __bfloat162float(h1));
    __nv_bfloat16 l2 = __float2bfloat16(v.z - __bfloat162float(h2));
    __nv_bfloat16 l3 = __float2bfloat16(v.w - __bfloat162float(h3));
    __nv_bfloat162 hp0 = __nv_bfloat162(h0, h1), hp1 = __nv_bfloat162(h2, h3);
    __nv_bfloat162 lp0 = __nv_bfloat162(l0, l1), lp1 = __nv_bfloat162(l2, l3);
    uint2 hv, lv;
    hv.x = *reinterpret_cast<uint32_t*>(&hp0); hv.y = *reinterpret_cast<uint32_t*>(&hp1);
    lv.x = *reinterpret_cast<uint32_t*>(&lp0); lv.y = *reinterpret_cast<uint32_t*>(&lp1);
    reinterpret_cast<uint2*>(g_Wh)[t] = hv;
    reinterpret_cast<uint2*>(g_Wl)[t] = lv;
}

// ---------------- gated hi/lo split of x: A[b, k*DIN+d] = c[b,k]*x[k,b,d] ----------------
__global__ void split_a_kernel(const float* __restrict__ x)
{
    const int t = blockIdx.x * blockDim.x + threadIdx.x;   // over KMOD*BDIM*DIN/4
    const int d4  = t & (DIN / 4 - 1);
    const int rem = t >> 8;
    const int b   = rem & (BDIM - 1);
    const int mod = rem >> 12;
    const float cc = g_c[b * KMOD + mod];
    float4 v = reinterpret_cast<const float4*>(x)[t];
    v.x *= cc; v.y *= cc; v.z *= cc; v.w *= cc;
    __nv_bfloat16 h0 = __float2bfloat16(v.x), h1 = __float2bfloat16(v.y);
    __nv_bfloat16 h2 = __float2bfloat16(v.z), h3 = __float2bfloat16(v.w);
    __nv_bfloat16 l0 = __float2bfloat16(v.x - __bfloat162float(h0));
    __nv_bfloat16 l1 = __float2bfloat16(v.y - __bfloat162float(h1));
    __nv_bfloat16 l2 = __float2bfloat16(v.z - __bfloat162float(h2));
    __nv_bfloat16 l3 = __float2bfloat16(v.w - __bfloat162float(h3));
    __nv_bfloat162 hp0 = __nv_bfloat162(h0, h1), hp1 = __nv_bfloat162(h2, h3);
    __nv_bfloat162 lp0 = __nv_bfloat162(l0, l1), lp1 = __nv_bfloat162(l2, l3);
    uint2 hv, lv;
    hv.x = *reinterpret_cast<uint32_t*>(&hp0); hv.y = *reinterpret_cast<uint32_t*>(&hp1);
    lv.x = *reinterpret_cast<uint32_t*>(&lp0); lv.y = *reinterpret_cast<uint32_t*>(&lp1);
    const size_t aidx4 = ((size_t)b * KDIM + (size_t)mod * DIN) / 4 + d4;
    reinterpret_cast<uint2*>(g_Ah)[aidx4] = hv;
    reinterpret_cast<uint2*>(g_Al)[aidx4] = lv;
}

// ---------------- main GEMM: out = Ah*Wh + Ah*Wl + Al*Wh + bias ----------------
#define BM 128
#define BN 128
#define BK 32
#define KT (KDIM / BK)                /* 128 iterations */
#define NSTAGE 4
#define ASTR 40                       /* bf16 units; 80B row stride */
#define BSTR 136                      /* bf16 units; 272B row stride */
#define A_BYTES (BM * ASTR * 2)       /* 10240 */
#define B_BYTES (BK * BSTR * 2)       /* 8704  */
#define OFF_B   (2 * A_BYTES)         /* 20480 */
#define STAGE_BYTES (2 * A_BYTES + 2 * B_BYTES)  /* 37888 */

__device__ __forceinline__ void cp16(uint32_t dst, const void* src)
{
    asm volatile("cp.async.cg.shared.global [%0], [%1], 16;\n" :: "r"(dst), "l"(src));
}
__device__ __forceinline__ void ldsm4(uint32_t* r, uint32_t addr)
{
    asm volatile("ldmatrix.sync.aligned.m8n8.x4.shared.b16 {%0,%1,%2,%3}, [%4];\n"
                 : "=r"(r[0]), "=r"(r[1]), "=r"(r[2]), "=r"(r[3]) : "r"(addr));
}
__device__ __forceinline__ void ldsm4t(uint32_t* r, uint32_t addr)
{
    asm volatile("ldmatrix.sync.aligned.m8n8.x4.trans.shared.b16 {%0,%1,%2,%3}, [%4];\n"
                 : "=r"(r[0]), "=r"(r[1]), "=r"(r[2]), "=r"(r[3]) : "r"(addr));
}
__device__ __forceinline__ void mma16816(float* d, const uint32_t* a, const uint32_t* b)
{
    asm volatile("mma.sync.aligned.m16n8k16.row.col.f32.bf16.bf16.f32 "
                 "{%0,%1,%2,%3},{%4,%5,%6,%7},{%8,%9},{%0,%1,%2,%3};\n"
                 : "+f"(d[0]), "+f"(d[1]), "+f"(d[2]), "+f"(d[3])
                 : "r"(a[0]), "r"(a[1]), "r"(a[2]), "r"(a[3]), "r"(b[0]), "r"(b[1]));
}

__global__ void __launch_bounds__(256, 1)
gemm_kernel(float* __restrict__ out, const float* __restrict__ b_enc)
{
    extern __shared__ char smem[];
    const int tid = threadIdx.x;
    const int warp = tid >> 5, lane = tid & 31;
    const int n0 = blockIdx.x * BN;
    const int m0 = blockIdx.y * BM;
    const int wm = warp & 1, wn = warp >> 1;   // 2 (M) x 4 (N) warps; warp tile 64x32

    const uint32_t sbase = (uint32_t)__cvta_generic_to_shared(smem);

    float d[4][4][4];
#pragma unroll
    for (int mt = 0; mt < 4; mt++)
#pragma unroll
        for (int nt = 0; nt < 4; nt++)
#pragma unroll
            for (int i = 0; i < 4; i++) d[mt][nt][i] = 0.0f;

    auto loadStage = [&](int s, int kt) {
        const uint32_t st = sbase + (uint32_t)s * STAGE_BYTES;
        const int bk = kt * BK;
#pragma unroll
        for (int i = 0; i < 4; i++) {                 // A: 1024 x 16B chunks
            const int idx = i * 256 + tid;
            const int var = idx >> 9, rem = idx & 511;
            const int r = rem >> 2, c = rem & 3;
            const __nv_bfloat16* src = (var ? g_Al : g_Ah) + (size_t)(m0 + r) * KDIM + bk + c * 8;
            cp16(st + var * A_BYTES + (uint32_t)(r * ASTR + c * 8) * 2, src);
        }
#pragma unroll
        for (int i = 0; i < 4; i++) {                 // B: 1024 x 16B chunks
            const int idx = i * 256 + tid;
            const int var = idx >> 9, rem = idx & 511;
            const int r = rem >> 4, c = rem & 15;
            const __nv_bfloat16* src = (var ? g_Wl : g_Wh) + (size_t)(bk + r) * HDIM + n0 + c * 8;
            cp16(st + OFF_B + var * B_BYTES + (uint32_t)(r * BSTR + c * 8) * 2, src);
        }
        asm volatile("cp.async.commit_group;\n");
    };

    loadStage(0, 0);
    loadStage(1, 1);
    loadStage(2, 2);

    for (int kt = 0; kt < KT; kt++) {
        if      (kt < KT - 2) asm volatile("cp.async.wait_group 2;\n");
        else if (kt < KT - 1) asm volatile("cp.async.wait_group 1;\n");
        else                  asm volatile("cp.async.wait_group 0;\n");
        __syncthreads();

        if (kt + 3 < KT) loadStage((kt + 3) & (NSTAGE - 1), kt + 3);

        const uint32_t st = sbase + (uint32_t)(kt & (NSTAGE - 1)) * STAGE_BYTES;
#pragma unroll
        for (int ks = 0; ks < 2; ks++) {
            uint32_t ah[4][4], al[4][4], bh[2][4], bl[2][4];
            // A fragments: 4 m16 tiles, hi+lo
#pragma unroll
            for (int mt = 0; mt < 4; mt++) {
                const int r = wm * 64 + mt * 16 + (lane & 15);
                const int cidx = ks * 16 + (lane >> 4) * 8;
                const uint32_t ao = (uint32_t)(r * ASTR + cidx) * 2;
                ldsm4(ah[mt], st + ao);
                ldsm4(al[mt], st + A_BYTES + ao);
            }
            // B fragments: 2 n16 groups, hi+lo
            const int part = lane >> 3;
            const int kr = ks * 16 + (part & 1) * 8 + (lane & 7);
#pragma unroll
            for (int grp = 0; grp < 2; grp++) {
                const int ncol = wn * 32 + grp * 16 + (part >> 1) * 8;
                const uint32_t bo = st + OFF_B + (uint32_t)(kr * BSTR + ncol) * 2;
                ldsm4t(bh[grp], bo);
                ldsm4t(bl[grp], bo + B_BYTES);
            }
            // term-major MMA ordering: each accumulator revisited after 16 MMAs
#pragma unroll
            for (int mt = 0; mt < 4; mt++)
#pragma unroll
                for (int grp = 0; grp < 2; grp++)
#pragma unroll
                    for (int nt2 = 0; nt2 < 2; nt2++)
                        mma16816(d[mt][grp * 2 + nt2], ah[mt], &bh[grp][nt2 * 2]);
#pragma unroll
            for (int mt = 0; mt < 4; mt++)
#pragma unroll
                for (int grp = 0; grp < 2; grp++)
#pragma unroll
                    for (int nt2 = 0; nt2 < 2; nt2++)
                        mma16816(d[mt][grp * 2 + nt2], ah[mt], &bl[grp][nt2 * 2]);
#pragma unroll
            for (int mt = 0; mt < 4; mt++)
#pragma unroll
                for (int grp = 0; grp < 2; grp++)
#pragma unroll
                    for (int nt2 = 0; nt2 < 2; nt2++)
                        mma16816(d[mt][grp * 2 + nt2], al[mt], &bh[grp][nt2 * 2]);
        }
        __syncthreads();
    }

    // epilogue: + sum_k c[b,k]*b_enc[k,h]
#pragma unroll
    for (int mt = 0; mt < 4; mt++) {
        const int rbase = m0 + wm * 64 + mt * 16 + (lane >> 2);
#pragma unroll
        for (int half = 0; half < 2; half++) {
            const int r = rbase + half * 8;
            const float4 c4 = *reinterpret_cast<const float4*>(&g_c[r * KMOD]);
#pragma unroll
            for (int nt = 0; nt < 4; nt++) {
                const int c = n0 + wn * 32 + nt * 8 + (lane & 3) * 2;
                const float bias0 = c4.x * b_enc[0 * HDIM + c]     + c4.y * b_enc[1 * HDIM + c]
                                  + c4.z * b_enc[2 * HDIM + c]     + c4.w * b_enc[3 * HDIM + c];
                const float bias1 = c4.x * b_enc[0 * HDIM + c + 1] + c4.y * b_enc[1 * HDIM + c + 1]
                                  + c4.z * b_enc[2 * HDIM + c + 1] + c4.w * b_enc[3 * HDIM + c + 1];
                float2 o;
                o.x = d[mt][nt][half * 2 + 0] + bias0;
                o.y = d[mt][nt][half * 2 + 1] + bias1;
                *reinterpret_cast<float2*>(out + (size_t)r * HDIM + c) = o;
            }
        }
    }
}

// ---------------- launch ----------------
extern "C" void kernel_launch(void* const* d_in, const int* in_sizes, int n_in,
                              void* d_out, int out_size)
{
    const float* context  = (const float*)d_in[0];
    const float* x        = (const float*)d_in[1];
    const float* gumbel   = (const float*)d_in[2];
    const float* W1       = (const float*)d_in[3];
    const float* b1       = (const float*)d_in[4];
    const float* gln      = (const float*)d_in[5];
    const float* bln      = (const float*)d_in[6];
    const float* W2       = (const float*)d_in[7];
    const float* b2       = (const float*)d_in[8];
    const float* W3       = (const float*)d_in[9];
    const float* b3       = (const float*)d_in[10];
    const float* prior    = (const float*)d_in[11];
    const float* W_enc    = (const float*)d_in[12];
    const float* b_enc    = (const float*)d_in[13];
    const float* fusion_w = (const float*)d_in[14];
    float* out = (float*)d_out;

    router_kernel<<<BDIM / 8, 256>>>(context, gumbel, W1, b1, gln, bln, W2, b2, W3, b3,
                                     prior, fusion_w);
    split_a_kernel<<<(KMOD * BDIM * (DIN / 4)) / 256, 256>>>(x);
    split_w_kernel<<<(KDIM * (HDIM / 4)) / 256, 256>>>(W_enc);

    const int dyn = NSTAGE * STAGE_BYTES;   // 151552
    cudaFuncSetAttribute(gemm_kernel, cudaFuncAttributeMaxDynamicSharedMemorySize, dyn);
    gemm_kernel<<<dim3(HDIM / BN, BDIM / BM), 256, dyn>>>(out, b_enc);
}

// round 4
// speedup vs baseline: 1.6741x; 1.6741x over previous
#include <cuda_runtime.h>
#include <cuda_fp16.h>
#include <cstdint>

#define BDIM 4096
#define KMOD 4
#define DIN  1024
#define HDIM 1024
#define CTXD 256
#define RHD  64
#define KDIM 4096  /* KMOD*DIN : concatenated reduction dim */

// ---------------- scratch (device globals: no runtime allocation) ----------------
__device__ float   g_c[BDIM * KMOD];                  // gate coeff c[b,k]
__device__ __half  g_A[(size_t)BDIM * KDIM];          // fp16(c*x)   [B][K]
__device__ __half  g_W[(size_t)KDIM * HDIM];          // fp16(W_enc) [K][H]

// ---------------- router: Linear->LN->ReLU->Linear->ReLU->Linear->gate ----------------
__global__ void router_kernel(const float* __restrict__ context,
                              const float* __restrict__ gumbel,
                              const float* __restrict__ W1, const float* __restrict__ b1,
                              const float* __restrict__ gln, const float* __restrict__ bln,
                              const float* __restrict__ W2, const float* __restrict__ b2,
                              const float* __restrict__ W3, const float* __restrict__ b3,
                              const float* __restrict__ prior,
                              const float* __restrict__ fusion_w)
{
    __shared__ float ctx_s[8][CTXD];
    __shared__ float h1_s[8][RHD];
    __shared__ float h2_s[8][RHD / 2];
    const int warp = threadIdx.x >> 5, lane = threadIdx.x & 31;
    const int b = blockIdx.x * 8 + warp;

    const float* crow = context + (size_t)b * CTXD;
    for (int i = lane; i < CTXD; i += 32) ctx_s[warp][i] = crow[i];
    __syncwarp();

    float h[2];
#pragma unroll
    for (int jj = 0; jj < 2; jj++) {
        const int j = lane + jj * 32;
        float acc = b1[j];
        for (int i = 0; i < CTXD; i++) acc = fmaf(ctx_s[warp][i], W1[i * RHD + j], acc);
        h[jj] = acc;
    }
    float s  = h[0] + h[1];
    float sq = h[0] * h[0] + h[1] * h[1];
#pragma unroll
    for (int o = 16; o; o >>= 1) {
        s  += __shfl_xor_sync(0xffffffffu, s,  o);
        sq += __shfl_xor_sync(0xffffffffu, sq, o);
    }
    const float mu   = s * (1.0f / RHD);
    const float var  = sq * (1.0f / RHD) - mu * mu;
    const float rstd = rsqrtf(var + 1e-5f);
#pragma unroll
    for (int jj = 0; jj < 2; jj++) {
        const int j = lane + jj * 32;
        const float v = (h[jj] - mu) * rstd * gln[j] + bln[j];
        h1_s[warp][j] = fmaxf(v, 0.0f);
    }
    __syncwarp();
    float acc2 = b2[lane];
    for (int i = 0; i < RHD; i++) acc2 = fmaf(h1_s[warp][i], W2[i * (RHD / 2) + lane], acc2);
    h2_s[warp][lane] = fmaxf(acc2, 0.0f);
    __syncwarp();

    float logit = 0.0f;
    if (lane < KMOD) {
        logit = b3[lane] + prior[lane];
        for (int i = 0; i < RHD / 2; i++) logit = fmaf(h2_s[warp][i], W3[i * KMOD + lane], logit);
    }
    float lg[4];
#pragma unroll
    for (int k = 0; k < 4; k++) lg[k] = __shfl_sync(0xffffffffu, logit, k);

    if (lane == 0) {
        float fw[4], m = -1e30f;
#pragma unroll
        for (int k = 0; k < 4; k++) { fw[k] = fusion_w[k]; m = fmaxf(m, fw[k]); }
        float se = 0.0f;
#pragma unroll
        for (int k = 0; k < 4; k++) { fw[k] = expf(fw[k] - m); se += fw[k]; }
        const float inv = 1.0f / se;
        int i1 = 0;
#pragma unroll
        for (int k = 1; k < 4; k++) if (lg[k] > lg[i1]) i1 = k;
        int i2 = (i1 == 0) ? 1 : 0;
#pragma unroll
        for (int k = 0; k < 4; k++) if (k != i1 && lg[k] > lg[i2]) i2 = k;
#pragma unroll
        for (int k = 0; k < 4; k++) {
            const float soft = 1.0f / (1.0f + expf(-(lg[k] + gumbel[b * KMOD + k])));
            const float mask = (k == i1 || k == i2) ? fmaxf(soft, 1.0f) : soft;
            const float cc   = (mask > 0.5f) ? (fw[k] * inv) * mask : 0.0f;
            g_c[b * KMOD + k] = cc;
        }
    }
}

// ---------------- fp16 convert of W_enc (layout [k*DIN+d][h]) ----------------
__global__ void conv_w_kernel(const float* __restrict__ W)
{
    const size_t t = (size_t)blockIdx.x * blockDim.x + threadIdx.x;   // over KDIM*HDIM/4
    const float4 v = reinterpret_cast<const float4*>(W)[t];
    __half2 p0 = __halves2half2(__float2half_rn(v.x), __float2half_rn(v.y));
    __half2 p1 = __halves2half2(__float2half_rn(v.z), __float2half_rn(v.w));
    uint2 o;
    o.x = *reinterpret_cast<uint32_t*>(&p0);
    o.y = *reinterpret_cast<uint32_t*>(&p1);
    reinterpret_cast<uint2*>(g_W)[t] = o;
}

// ---------------- gated fp16 convert of x: A[b, k*DIN+d] = c[b,k]*x[k,b,d] ----------------
__global__ void conv_a_kernel(const float* __restrict__ x)
{
    const int t = blockIdx.x * blockDim.x + threadIdx.x;   // over KMOD*BDIM*DIN/4
    const int d4  = t & (DIN / 4 - 1);
    const int rem = t >> 8;
    const int b   = rem & (BDIM - 1);
    const int mod = rem >> 12;
    const float cc = g_c[b * KMOD + mod];
    float4 v = reinterpret_cast<const float4*>(x)[t];
    __half2 p0 = __halves2half2(__float2half_rn(v.x * cc), __float2half_rn(v.y * cc));
    __half2 p1 = __halves2half2(__float2half_rn(v.z * cc), __float2half_rn(v.w * cc));
    uint2 o;
    o.x = *reinterpret_cast<uint32_t*>(&p0);
    o.y = *reinterpret_cast<uint32_t*>(&p1);
    const size_t aidx4 = ((size_t)b * KDIM + (size_t)mod * DIN) / 4 + d4;
    reinterpret_cast<uint2*>(g_A)[aidx4] = o;
}

// ---------------- main GEMM (single-pass fp16): out = A*W + bias ----------------
#define BM 128
#define BN 128
#define BK 64
#define KT (KDIM / BK)                /* 64 iterations */
#define NSTAGE 3
#define ASTR 72                       /* fp16 units; 144B row stride -> conflict-free */
#define BSTR 136                      /* fp16 units; 272B row stride */
#define A_BYTES (BM * ASTR * 2)       /* 18432 */
#define B_BYTES (BK * BSTR * 2)       /* 17408 */
#define OFF_B   A_BYTES
#define STAGE_BYTES (A_BYTES + B_BYTES)  /* 35840 */

__device__ __forceinline__ void cp16(uint32_t dst, const void* src)
{
    asm volatile("cp.async.cg.shared.global [%0], [%1], 16;\n" :: "r"(dst), "l"(src));
}
__device__ __forceinline__ void ldsm4(uint32_t* r, uint32_t addr)
{
    asm volatile("ldmatrix.sync.aligned.m8n8.x4.shared.b16 {%0,%1,%2,%3}, [%4];\n"
                 : "=r"(r[0]), "=r"(r[1]), "=r"(r[2]), "=r"(r[3]) : "r"(addr));
}
__device__ __forceinline__ void ldsm4t(uint32_t* r, uint32_t addr)
{
    asm volatile("ldmatrix.sync.aligned.m8n8.x4.trans.shared.b16 {%0,%1,%2,%3}, [%4];\n"
                 : "=r"(r[0]), "=r"(r[1]), "=r"(r[2]), "=r"(r[3]) : "r"(addr));
}
__device__ __forceinline__ void mma16816(float* d, const uint32_t* a, const uint32_t* b)
{
    asm volatile("mma.sync.aligned.m16n8k16.row.col.f32.f16.f16.f32 "
                 "{%0,%1,%2,%3},{%4,%5,%6,%7},{%8,%9},{%0,%1,%2,%3};\n"
                 : "+f"(d[0]), "+f"(d[1]), "+f"(d[2]), "+f"(d[3])
                 : "r"(a[0]), "r"(a[1]), "r"(a[2]), "r"(a[3]), "r"(b[0]), "r"(b[1]));
}

__global__ void __launch_bounds__(256, 2)
gemm_kernel(float* __restrict__ out, const float* __restrict__ b_enc)
{
    extern __shared__ char smem[];
    const int tid = threadIdx.x;
    const int warp = tid >> 5, lane = tid & 31;
    const int n0 = blockIdx.x * BN;
    const int m0 = blockIdx.y * BM;
    const int wm = warp & 1, wn = warp >> 1;   // 2 (M) x 4 (N) warps; warp tile 64x32

    const uint32_t sbase = (uint32_t)__cvta_generic_to_shared(smem);

    float d[4][4][4];
#pragma unroll
    for (int mt = 0; mt < 4; mt++)
#pragma unroll
        for (int nt = 0; nt < 4; nt++)
#pragma unroll
            for (int i = 0; i < 4; i++) d[mt][nt][i] = 0.0f;

    auto loadStage = [&](int s, int kt) {
        const uint32_t st = sbase + (uint32_t)s * STAGE_BYTES;
        const int bk = kt * BK;
#pragma unroll
        for (int i = 0; i < 4; i++) {                 // A: 1024 x 16B chunks (128 x 64 fp16)
            const int idx = i * 256 + tid;
            const int r = idx >> 3, c = idx & 7;
            const __half* src = g_A + (size_t)(m0 + r) * KDIM + bk + c * 8;
            cp16(st + (uint32_t)(r * ASTR + c * 8) * 2, src);
        }
#pragma unroll
        for (int i = 0; i < 4; i++) {                 // B: 1024 x 16B chunks (64 x 128 fp16)
            const int idx = i * 256 + tid;
            const int r = idx >> 4, c = idx & 15;
            const __half* src = g_W + (size_t)(bk + r) * HDIM + n0 + c * 8;
            cp16(st + OFF_B + (uint32_t)(r * BSTR + c * 8) * 2, src);
        }
        asm volatile("cp.async.commit_group;\n");
    };

    loadStage(0, 0);
    loadStage(1, 1);

    for (int kt = 0; kt < KT; kt++) {
        if (kt + 1 < KT) asm volatile("cp.async.wait_group 1;\n");
        else             asm volatile("cp.async.wait_group 0;\n");
        __syncthreads();

        if (kt + 2 < KT) loadStage((kt + 2) % NSTAGE, kt + 2);

        const uint32_t st = sbase + (uint32_t)(kt % NSTAGE) * STAGE_BYTES;
#pragma unroll
        for (int ks = 0; ks < 4; ks++) {
            uint32_t a[4][4], bfr[2][4];
#pragma unroll
            for (int mt = 0; mt < 4; mt++) {
                const int r = wm * 64 + mt * 16 + (lane & 15);
                const int cidx = ks * 16 + (lane >> 4) * 8;
                ldsm4(a[mt], st + (uint32_t)(r * ASTR + cidx) * 2);
            }
            const int part = lane >> 3;
            const int kr = ks * 16 + (part & 1) * 8 + (lane & 7);
#pragma unroll
            for (int grp = 0; grp < 2; grp++) {
                const int ncol = wn * 32 + grp * 16 + (part >> 1) * 8;
                ldsm4t(bfr[grp], st + OFF_B + (uint32_t)(kr * BSTR + ncol) * 2);
            }
#pragma unroll
            for (int mt = 0; mt < 4; mt++)
#pragma unroll
                for (int grp = 0; grp < 2; grp++)
#pragma unroll
                    for (int nt2 = 0; nt2 < 2; nt2++)
                        mma16816(d[mt][grp * 2 + nt2], a[mt], &bfr[grp][nt2 * 2]);
        }
    }

    // epilogue: + sum_k c[b,k]*b_enc[k,h]
#pragma unroll
    for (int mt = 0; mt < 4; mt++) {
        const int rbase = m0 + wm * 64 + mt * 16 + (lane >> 2);
#pragma unroll
        for (int half = 0; half < 2; half++) {
            const int r = rbase + half * 8;
            const float4 c4 = *reinterpret_cast<const float4*>(&g_c[r * KMOD]);
#pragma unroll
            for (int nt = 0; nt < 4; nt++) {
                const int c = n0 + wn * 32 + nt * 8 + (lane & 3) * 2;
                const float bias0 = c4.x * b_enc[0 * HDIM + c]     + c4.y * b_enc[1 * HDIM + c]
                                  + c4.z * b_enc[2 * HDIM + c]     + c4.w * b_enc[3 * HDIM + c];
                const float bias1 = c4.x * b_enc[0 * HDIM + c + 1] + c4.y * b_enc[1 * HDIM + c + 1]
                                  + c4.z * b_enc[2 * HDIM + c + 1] + c4.w * b_enc[3 * HDIM + c + 1];
                float2 o;
                o.x = d[mt][nt][half * 2 + 0] + bias0;
                o.y = d[mt][nt][half * 2 + 1] + bias1;
                *reinterpret_cast<float2*>(out + (size_t)r * HDIM + c) = o;
            }
        }
    }
}

// ---------------- launch ----------------
extern "C" void kernel_launch(void* const* d_in, const int* in_sizes, int n_in,
                              void* d_out, int out_size)
{
    const float* context  = (const float*)d_in[0];
    const float* x        = (const float*)d_in[1];
    const float* gumbel   = (const float*)d_in[2];
    const float* W1       = (const float*)d_in[3];
    const float* b1       = (const float*)d_in[4];
    const float* gln      = (const float*)d_in[5];
    const float* bln      = (const float*)d_in[6];
    const float* W2       = (const float*)d_in[7];
    const float* b2       = (const float*)d_in[8];
    const float* W3       = (const float*)d_in[9];
    const float* b3       = (const float*)d_in[10];
    const float* prior    = (const float*)d_in[11];
    const float* W_enc    = (const float*)d_in[12];
    const float* b_enc    = (const float*)d_in[13];
    const float* fusion_w = (const float*)d_in[14];
    float* out = (float*)d_out;

    router_kernel<<<BDIM / 8, 256>>>(context, gumbel, W1, b1, gln, bln, W2, b2, W3, b3,
                                     prior, fusion_w);
    conv_a_kernel<<<(KMOD * BDIM * (DIN / 4)) / 256, 256>>>(x);
    conv_w_kernel<<<(KDIM * (HDIM / 4)) / 256, 256>>>(W_enc);

    const int dyn = NSTAGE * STAGE_BYTES;   // 107520
    cudaFuncSetAttribute(gemm_kernel, cudaFuncAttributeMaxDynamicSharedMemorySize, dyn);
    gemm_kernel<<<dim3(HDIM / BN, BDIM / BM), 256, dyn>>>(out, b_enc);
}

// round 5
// speedup vs baseline: 2.4145x; 1.4423x over previous
#include <cuda_runtime.h>
#include <cuda_fp16.h>
#include <cstdint>

#define BDIM 4096
#define KMOD 4
#define DIN  1024
#define HDIM 1024
#define CTXD 256
#define RHD  64
#define KDIM 4096  /* KMOD*DIN : concatenated reduction dim */

// ---------------- scratch (device globals: no runtime allocation) ----------------
__device__ float   g_c[BDIM * KMOD];                  // gate coeff c[b,k]
__device__ __half  g_A[(size_t)BDIM * KDIM];          // fp16(c*x)   [B][K]
__device__ __half  g_W[(size_t)KDIM * HDIM];          // fp16(W_enc) [K][H]

// ---------------- router: W1/W2/W3 cached in smem, 16 rows/block ----------------
#define RROWS 16
__global__ void router_kernel(const float* __restrict__ context,
                              const float* __restrict__ gumbel,
                              const float* __restrict__ W1, const float* __restrict__ b1,
                              const float* __restrict__ gln, const float* __restrict__ bln,
                              const float* __restrict__ W2, const float* __restrict__ b2,
                              const float* __restrict__ W3, const float* __restrict__ b3,
                              const float* __restrict__ prior,
                              const float* __restrict__ fusion_w)
{
    extern __shared__ float rs[];
    float* w1_s  = rs;                       // 16384
    float* w2_s  = w1_s + CTXD * RHD;        // 2048
    float* w3_s  = w2_s + RHD * (RHD / 2);   // 128
    float* ctx_s = w3_s + (RHD / 2) * KMOD;  // 4096
    float* h1_s  = ctx_s + RROWS * CTXD;     // 1024
    float* h2_s  = h1_s + RROWS * RHD;       // 512

    const int tid = threadIdx.x;
    const int warp = tid >> 5, lane = tid & 31;
    const int b0 = blockIdx.x * RROWS;

    for (int i = tid; i < CTXD * RHD / 4; i += 256)
        reinterpret_cast<float4*>(w1_s)[i] = reinterpret_cast<const float4*>(W1)[i];
    for (int i = tid; i < RHD * (RHD / 2) / 4; i += 256)
        reinterpret_cast<float4*>(w2_s)[i] = reinterpret_cast<const float4*>(W2)[i];
    if (tid < (RHD / 2) * KMOD / 4)
        reinterpret_cast<float4*>(w3_s)[tid] = reinterpret_cast<const float4*>(W3)[tid];
    for (int i = tid; i < RROWS * CTXD / 4; i += 256)
        reinterpret_cast<float4*>(ctx_s)[i] =
            reinterpret_cast<const float4*>(context + (size_t)b0 * CTXD)[i];
    __syncthreads();

#pragma unroll
    for (int rr = 0; rr < 2; rr++) {
        const int row = warp + rr * 8;         // local row, 8 warps x 2 passes
        const float* crow = ctx_s + row * CTXD;

        float h[2];
#pragma unroll
        for (int jj = 0; jj < 2; jj++) {
            const int j = lane + jj * 32;
            float acc = b1[j];
            for (int i = 0; i < CTXD; i++) acc = fmaf(crow[i], w1_s[i * RHD + j], acc);
            h[jj] = acc;
        }
        float s  = h[0] + h[1];
        float sq = h[0] * h[0] + h[1] * h[1];
#pragma unroll
        for (int o = 16; o; o >>= 1) {
            s  += __shfl_xor_sync(0xffffffffu, s,  o);
            sq += __shfl_xor_sync(0xffffffffu, sq, o);
        }
        const float mu   = s * (1.0f / RHD);
        const float var  = sq * (1.0f / RHD) - mu * mu;
        const float rstd = rsqrtf(var + 1e-5f);
#pragma unroll
        for (int jj = 0; jj < 2; jj++) {
            const int j = lane + jj * 32;
            const float v = (h[jj] - mu) * rstd * gln[j] + bln[j];
            h1_s[row * RHD + j] = fmaxf(v, 0.0f);
        }
        __syncwarp();
        float acc2 = b2[lane];
        for (int i = 0; i < RHD; i++)
            acc2 = fmaf(h1_s[row * RHD + i], w2_s[i * (RHD / 2) + lane], acc2);
        h2_s[row * (RHD / 2) + lane] = fmaxf(acc2, 0.0f);
        __syncwarp();

        float logit = 0.0f;
        if (lane < KMOD) {
            logit = b3[lane] + prior[lane];
            for (int i = 0; i < RHD / 2; i++)
                logit = fmaf(h2_s[row * (RHD / 2) + i], w3_s[i * KMOD + lane], logit);
        }
        float lg[4];
#pragma unroll
        for (int k = 0; k < 4; k++) lg[k] = __shfl_sync(0xffffffffu, logit, k);

        if (lane == 0) {
            const int b = b0 + row;
            float fw[4], m = -1e30f;
#pragma unroll
            for (int k = 0; k < 4; k++) { fw[k] = fusion_w[k]; m = fmaxf(m, fw[k]); }
            float se = 0.0f;
#pragma unroll
            for (int k = 0; k < 4; k++) { fw[k] = expf(fw[k] - m); se += fw[k]; }
            const float inv = 1.0f / se;
            int i1 = 0;
#pragma unroll
            for (int k = 1; k < 4; k++) if (lg[k] > lg[i1]) i1 = k;
            int i2 = (i1 == 0) ? 1 : 0;
#pragma unroll
            for (int k = 0; k < 4; k++) if (k != i1 && lg[k] > lg[i2]) i2 = k;
#pragma unroll
            for (int k = 0; k < 4; k++) {
                const float soft = 1.0f / (1.0f + expf(-(lg[k] + gumbel[b * KMOD + k])));
                const float mask = (k == i1 || k == i2) ? fmaxf(soft, 1.0f) : soft;
                const float cc   = (mask > 0.5f) ? (fw[k] * inv) * mask : 0.0f;
                g_c[b * KMOD + k] = cc;
            }
        }
    }
}
#define ROUTER_SMEM ((CTXD * RHD + RHD * (RHD / 2) + (RHD / 2) * KMOD \
                      + RROWS * CTXD + RROWS * RHD + RROWS * (RHD / 2)) * 4)

// ---------------- fp16 convert of W_enc (layout [k*DIN+d][h]) ----------------
__global__ void conv_w_kernel(const float* __restrict__ W)
{
    const size_t t = (size_t)blockIdx.x * blockDim.x + threadIdx.x;   // over KDIM*HDIM/4
    const float4 v = reinterpret_cast<const float4*>(W)[t];
    __half2 p0 = __halves2half2(__float2half_rn(v.x), __float2half_rn(v.y));
    __half2 p1 = __halves2half2(__float2half_rn(v.z), __float2half_rn(v.w));
    uint2 o;
    o.x = *reinterpret_cast<uint32_t*>(&p0);
    o.y = *reinterpret_cast<uint32_t*>(&p1);
    reinterpret_cast<uint2*>(g_W)[t] = o;
}

// ---------------- gated fp16 convert of x: A[b, k*DIN+d] = c[b,k]*x[k,b,d] ----------------
__global__ void conv_a_kernel(const float* __restrict__ x)
{
    const int t = blockIdx.x * blockDim.x + threadIdx.x;   // over KMOD*BDIM*DIN/4
    const int d4  = t & (DIN / 4 - 1);
    const int rem = t >> 8;
    const int b   = rem & (BDIM - 1);
    const int mod = rem >> 12;
    const float cc = g_c[b * KMOD + mod];
    float4 v = reinterpret_cast<const float4*>(x)[t];
    __half2 p0 = __halves2half2(__float2half_rn(v.x * cc), __float2half_rn(v.y * cc));
    __half2 p1 = __halves2half2(__float2half_rn(v.z * cc), __float2half_rn(v.w * cc));
    uint2 o;
    o.x = *reinterpret_cast<uint32_t*>(&p0);
    o.y = *reinterpret_cast<uint32_t*>(&p1);
    const size_t aidx4 = ((size_t)b * KDIM + (size_t)mod * DIN) / 4 + d4;
    reinterpret_cast<uint2*>(g_A)[aidx4] = o;
}

// ---------------- main GEMM: 64x64 warp tiles, occ 1, 4-stage ring ----------------
#define BM 128
#define BN 256
#define BK 64
#define KT (KDIM / BK)                /* 64 iterations */
#define NSTAGE 4
#define ASTR 72                       /* fp16 units; 144B row stride -> conflict-free */
#define BSTR 264                      /* fp16 units; 528B row stride */
#define A_BYTES (BM * ASTR * 2)       /* 18432 */
#define B_BYTES (BK * BSTR * 2)       /* 33792 */
#define OFF_B   A_BYTES
#define STAGE_BYTES (A_BYTES + B_BYTES)  /* 52224 */

__device__ __forceinline__ void cp16(uint32_t dst, const void* src)
{
    asm volatile("cp.async.cg.shared.global [%0], [%1], 16;\n" :: "r"(dst), "l"(src));
}
__device__ __forceinline__ void ldsm4(uint32_t* r, uint32_t addr)
{
    asm volatile("ldmatrix.sync.aligned.m8n8.x4.shared.b16 {%0,%1,%2,%3}, [%4];\n"
                 : "=r"(r[0]), "=r"(r[1]), "=r"(r[2]), "=r"(r[3]) : "r"(addr));
}
__device__ __forceinline__ void ldsm4t(uint32_t* r, uint32_t addr)
{
    asm volatile("ldmatrix.sync.aligned.m8n8.x4.trans.shared.b16 {%0,%1,%2,%3}, [%4];\n"
                 : "=r"(r[0]), "=r"(r[1]), "=r"(r[2]), "=r"(r[3]) : "r"(addr));
}
__device__ __forceinline__ void mma16816(float* d, const uint32_t* a, const uint32_t* b)
{
    asm volatile("mma.sync.aligned.m16n8k16.row.col.f32.f16.f16.f32 "
                 "{%0,%1,%2,%3},{%4,%5,%6,%7},{%8,%9},{%0,%1,%2,%3};\n"
                 : "+f"(d[0]), "+f"(d[1]), "+f"(d[2]), "+f"(d[3])
                 : "r"(a[0]), "r"(a[1]), "r"(a[2]), "r"(a[3]), "r"(b[0]), "r"(b[1]));
}

__global__ void __launch_bounds__(256, 1)
gemm_kernel(float* __restrict__ out, const float* __restrict__ b_enc)
{
    extern __shared__ char smem[];
    const int tid = threadIdx.x;
    const int warp = tid >> 5, lane = tid & 31;
    const int n0 = blockIdx.x * BN;
    const int m0 = blockIdx.y * BM;
    const int wm = warp & 1, wn = warp >> 1;   // 2 (M) x 4 (N) warps; warp tile 64x64

    const uint32_t sbase = (uint32_t)__cvta_generic_to_shared(smem);

    float d[4][8][4];
#pragma unroll
    for (int mt = 0; mt < 4; mt++)
#pragma unroll
        for (int nt = 0; nt < 8; nt++)
#pragma unroll
            for (int i = 0; i < 4; i++) d[mt][nt][i] = 0.0f;

    auto loadStage = [&](int s, int kt) {
        const uint32_t st = sbase + (uint32_t)s * STAGE_BYTES;
        const int bk = kt * BK;
#pragma unroll
        for (int i = 0; i < 4; i++) {                 // A: 1024 x 16B (128 x 64 fp16)
            const int idx = i * 256 + tid;
            const int r = idx >> 3, c = idx & 7;
            const __half* src = g_A + (size_t)(m0 + r) * KDIM + bk + c * 8;
            cp16(st + (uint32_t)(r * ASTR + c * 8) * 2, src);
        }
#pragma unroll
        for (int i = 0; i < 8; i++) {                 // B: 2048 x 16B (64 x 256 fp16)
            const int idx = i * 256 + tid;
            const int r = idx >> 5, c = idx & 31;
            const __half* src = g_W + (size_t)(bk + r) * HDIM + n0 + c * 8;
            cp16(st + OFF_B + (uint32_t)(r * BSTR + c * 8) * 2, src);
        }
        asm volatile("cp.async.commit_group;\n");
    };

    uint32_t af[2][4][4], bf[2][4][4];
    auto loadFrags = [&](uint32_t st, int ks, int buf) {
#pragma unroll
        for (int mt = 0; mt < 4; mt++) {
            const int r = wm * 64 + mt * 16 + (lane & 15);
            const int c = ks * 16 + (lane >> 4) * 8;
            ldsm4(af[buf][mt], st + (uint32_t)(r * ASTR + c) * 2);
        }
        const int part = lane >> 3;
        const int kr = ks * 16 + (part & 1) * 8 + (lane & 7);
#pragma unroll
        for (int g = 0; g < 4; g++) {
            const int ncol = wn * 64 + g * 16 + (part >> 1) * 8;
            ldsm4t(bf[buf][g], st + OFF_B + (uint32_t)(kr * BSTR + ncol) * 2);
        }
    };

    loadStage(0, 0);
    loadStage(1, 1);
    loadStage(2, 2);

    for (int kt = 0; kt < KT; kt++) {
        if      (kt < KT - 2) asm volatile("cp.async.wait_group 2;\n");
        else if (kt < KT - 1) asm volatile("cp.async.wait_group 1;\n");
        else                  asm volatile("cp.async.wait_group 0;\n");
        __syncthreads();

        const uint32_t st = sbase + (uint32_t)(kt & (NSTAGE - 1)) * STAGE_BYTES;
        loadFrags(st, 0, 0);
        if (kt + 3 < KT) loadStage((kt + 3) & (NSTAGE - 1), kt + 3);

#pragma unroll
        for (int ks = 0; ks < 4; ks++) {
            if (ks < 3) loadFrags(st, ks + 1, (ks + 1) & 1);
            const int cur = ks & 1;
#pragma unroll
            for (int mt = 0; mt < 4; mt++)
#pragma unroll
                for (int g = 0; g < 4; g++)
#pragma unroll
                    for (int h = 0; h < 2; h++)
                        mma16816(d[mt][g * 2 + h], af[cur][mt], &bf[cur][g][h * 2]);
        }
    }

    // epilogue: + sum_k c[b,k]*b_enc[k,h]
#pragma unroll
    for (int mt = 0; mt < 4; mt++) {
        const int rbase = m0 + wm * 64 + mt * 16 + (lane >> 2);
#pragma unroll
        for (int half = 0; half < 2; half++) {
            const int r = rbase + half * 8;
            const float4 c4 = *reinterpret_cast<const float4*>(&g_c[r * KMOD]);
#pragma unroll
            for (int nt = 0; nt < 8; nt++) {
                const int c = n0 + wn * 64 + nt * 8 + (lane & 3) * 2;
                const float bias0 = c4.x * b_enc[0 * HDIM + c]     + c4.y * b_enc[1 * HDIM + c]
                                  + c4.z * b_enc[2 * HDIM + c]     + c4.w * b_enc[3 * HDIM + c];
                const float bias1 = c4.x * b_enc[0 * HDIM + c + 1] + c4.y * b_enc[1 * HDIM + c + 1]
                                  + c4.z * b_enc[2 * HDIM + c + 1] + c4.w * b_enc[3 * HDIM + c + 1];
                float2 o;
                o.x = d[mt][nt][half * 2 + 0] + bias0;
                o.y = d[mt][nt][half * 2 + 1] + bias1;
                *reinterpret_cast<float2*>(out + (size_t)r * HDIM + c) = o;
            }
        }
    }
}

// ---------------- launch ----------------
extern "C" void kernel_launch(void* const* d_in, const int* in_sizes, int n_in,
                              void* d_out, int out_size)
{
    const float* context  = (const float*)d_in[0];
    const float* x        = (const float*)d_in[1];
    const float* gumbel   = (const float*)d_in[2];
    const float* W1       = (const float*)d_in[3];
    const float* b1       = (const float*)d_in[4];
    const float* gln      = (const float*)d_in[5];
    const float* bln      = (const float*)d_in[6];
    const float* W2       = (const float*)d_in[7];
    const float* b2       = (const float*)d_in[8];
    const float* W3       = (const float*)d_in[9];
    const float* b3       = (const float*)d_in[10];
    const float* prior    = (const float*)d_in[11];
    const float* W_enc    = (const float*)d_in[12];
    const float* b_enc    = (const float*)d_in[13];
    const float* fusion_w = (const float*)d_in[14];
    float* out = (float*)d_out;

    cudaFuncSetAttribute(router_kernel, cudaFuncAttributeMaxDynamicSharedMemorySize,
                         ROUTER_SMEM);
    router_kernel<<<BDIM / RROWS, 256, ROUTER_SMEM>>>(context, gumbel, W1, b1, gln, bln,
                                                      W2, b2, W3, b3, prior, fusion_w);
    conv_a_kernel<<<(KMOD * BDIM * (DIN / 4)) / 256, 256>>>(x);
    conv_w_kernel<<<(KDIM * (HDIM / 4)) / 256, 256>>>(W_enc);

    const int dyn = NSTAGE * STAGE_BYTES;   // 208896
    cudaFuncSetAttribute(gemm_kernel, cudaFuncAttributeMaxDynamicSharedMemorySize, dyn);
    gemm_kernel<<<dim3(HDIM / BN, BDIM / BM), 256, dyn>>>(out, b_enc);
}

// round 6
// speedup vs baseline: 2.7217x; 1.1272x over previous
#include <cuda_runtime.h>
#include <cuda_fp16.h>
#include <cstdint>

#define BDIM 4096
#define KMOD 4
#define DIN  1024
#define HDIM 1024
#define CTXD 256
#define RHD  64
#define KDIM 4096  /* KMOD*DIN : concatenated reduction dim */

// ---------------- scratch (device globals: no runtime allocation) ----------------
__device__ float   g_c[BDIM * KMOD];                  // gate coeff c[b,k]
__device__ __half  g_A[(size_t)BDIM * KDIM];          // fp16(c*x)   [B][K]
__device__ __half  g_W[(size_t)KDIM * HDIM];          // fp16(W_enc) [K][H]

// ---------------- router (+ fused W_enc fp16 conversion) ----------------
#define RROWS 16
__global__ void router_kernel(const float* __restrict__ context,
                              const float* __restrict__ gumbel,
                              const float* __restrict__ W1, const float* __restrict__ b1,
                              const float* __restrict__ gln, const float* __restrict__ bln,
                              const float* __restrict__ W2, const float* __restrict__ b2,
                              const float* __restrict__ W3, const float* __restrict__ b3,
                              const float* __restrict__ prior,
                              const float* __restrict__ fusion_w,
                              const float* __restrict__ W_enc)
{
    extern __shared__ float rs[];
    float* w1_s  = rs;                       // 16384
    float* w2_s  = w1_s + CTXD * RHD;        // 2048
    float* w3_s  = w2_s + RHD * (RHD / 2);   // 128
    float* ctx_s = w3_s + (RHD / 2) * KMOD;  // 4096
    float* h1_s  = ctx_s + RROWS * CTXD;     // 1024
    float* h2_s  = h1_s + RROWS * RHD;       // 512

    const int tid = threadIdx.x;
    const int warp = tid >> 5, lane = tid & 31;
    const int b0 = blockIdx.x * RROWS;

    // --- fused: convert W_enc -> g_W fp16 (grid-stride, overlaps router compute) ---
    {
        const int gtid = blockIdx.x * 256 + tid;
#pragma unroll 4
        for (int i = gtid; i < KDIM * HDIM / 4; i += 256 * 256) {
            const float4 v = reinterpret_cast<const float4*>(W_enc)[i];
            __half2 p0 = __halves2half2(__float2half_rn(v.x), __float2half_rn(v.y));
            __half2 p1 = __halves2half2(__float2half_rn(v.z), __float2half_rn(v.w));
            uint2 o;
            o.x = *reinterpret_cast<uint32_t*>(&p0);
            o.y = *reinterpret_cast<uint32_t*>(&p1);
            reinterpret_cast<uint2*>(g_W)[i] = o;
        }
    }

    for (int i = tid; i < CTXD * RHD / 4; i += 256)
        reinterpret_cast<float4*>(w1_s)[i] = reinterpret_cast<const float4*>(W1)[i];
    for (int i = tid; i < RHD * (RHD / 2) / 4; i += 256)
        reinterpret_cast<float4*>(w2_s)[i] = reinterpret_cast<const float4*>(W2)[i];
    if (tid < (RHD / 2) * KMOD / 4)
        reinterpret_cast<float4*>(w3_s)[tid] = reinterpret_cast<const float4*>(W3)[tid];
    for (int i = tid; i < RROWS * CTXD / 4; i += 256)
        reinterpret_cast<float4*>(ctx_s)[i] =
            reinterpret_cast<const float4*>(context + (size_t)b0 * CTXD)[i];
    __syncthreads();

#pragma unroll
    for (int rr = 0; rr < 2; rr++) {
        const int row = warp + rr * 8;         // local row, 8 warps x 2 passes
        const float* crow = ctx_s + row * CTXD;

        float h[2];
#pragma unroll
        for (int jj = 0; jj < 2; jj++) {
            const int j = lane + jj * 32;
            float acc = b1[j];
            for (int i = 0; i < CTXD; i++) acc = fmaf(crow[i], w1_s[i * RHD + j], acc);
            h[jj] = acc;
        }
        float s  = h[0] + h[1];
        float sq = h[0] * h[0] + h[1] * h[1];
#pragma unroll
        for (int o = 16; o; o >>= 1) {
            s  += __shfl_xor_sync(0xffffffffu, s,  o);
            sq += __shfl_xor_sync(0xffffffffu, sq, o);
        }
        const float mu   = s * (1.0f / RHD);
        const float var  = sq * (1.0f / RHD) - mu * mu;
        const float rstd = rsqrtf(var + 1e-5f);
#pragma unroll
        for (int jj = 0; jj < 2; jj++) {
            const int j = lane + jj * 32;
            const float v = (h[jj] - mu) * rstd * gln[j] + bln[j];
            h1_s[row * RHD + j] = fmaxf(v, 0.0f);
        }
        __syncwarp();
        float acc2 = b2[lane];
        for (int i = 0; i < RHD; i++)
            acc2 = fmaf(h1_s[row * RHD + i], w2_s[i * (RHD / 2) + lane], acc2);
        h2_s[row * (RHD / 2) + lane] = fmaxf(acc2, 0.0f);
        __syncwarp();

        float logit = 0.0f;
        if (lane < KMOD) {
            logit = b3[lane] + prior[lane];
            for (int i = 0; i < RHD / 2; i++)
                logit = fmaf(h2_s[row * (RHD / 2) + i], w3_s[i * KMOD + lane], logit);
        }
        float lg[4];
#pragma unroll
        for (int k = 0; k < 4; k++) lg[k] = __shfl_sync(0xffffffffu, logit, k);

        if (lane == 0) {
            const int b = b0 + row;
            float fw[4], m = -1e30f;
#pragma unroll
            for (int k = 0; k < 4; k++) { fw[k] = fusion_w[k]; m = fmaxf(m, fw[k]); }
            float se = 0.0f;
#pragma unroll
            for (int k = 0; k < 4; k++) { fw[k] = expf(fw[k] - m); se += fw[k]; }
            const float inv = 1.0f / se;
            int i1 = 0;
#pragma unroll
            for (int k = 1; k < 4; k++) if (lg[k] > lg[i1]) i1 = k;
            int i2 = (i1 == 0) ? 1 : 0;
#pragma unroll
            for (int k = 0; k < 4; k++) if (k != i1 && lg[k] > lg[i2]) i2 = k;
#pragma unroll
            for (int k = 0; k < 4; k++) {
                const float soft = 1.0f / (1.0f + expf(-(lg[k] + gumbel[b * KMOD + k])));
                const float mask = (k == i1 || k == i2) ? fmaxf(soft, 1.0f) : soft;
                const float cc   = (mask > 0.5f) ? (fw[k] * inv) * mask : 0.0f;
                g_c[b * KMOD + k] = cc;
            }
        }
    }
}
#define ROUTER_SMEM ((CTXD * RHD + RHD * (RHD / 2) + (RHD / 2) * KMOD \
                      + RROWS * CTXD + RROWS * RHD + RROWS * (RHD / 2)) * 4)

// ---------------- gated fp16 convert of x: A[b, k*DIN+d] = c[b,k]*x[k,b,d] ----------------
__global__ void conv_a_kernel(const float* __restrict__ x)
{
    const int stride = gridDim.x * blockDim.x;
#pragma unroll 2
    for (int t = blockIdx.x * blockDim.x + threadIdx.x;
         t < KMOD * BDIM * (DIN / 4); t += stride) {
        const int d4  = t & (DIN / 4 - 1);
        const int rem = t >> 8;
        const int b   = rem & (BDIM - 1);
        const int mod = rem >> 12;
        const float cc = g_c[b * KMOD + mod];
        float4 v = reinterpret_cast<const float4*>(x)[t];
        __half2 p0 = __halves2half2(__float2half_rn(v.x * cc), __float2half_rn(v.y * cc));
        __half2 p1 = __halves2half2(__float2half_rn(v.z * cc), __float2half_rn(v.w * cc));
        uint2 o;
        o.x = *reinterpret_cast<uint32_t*>(&p0);
        o.y = *reinterpret_cast<uint32_t*>(&p1);
        const size_t aidx4 = ((size_t)b * KDIM + (size_t)mod * DIN) / 4 + d4;
        reinterpret_cast<uint2*>(g_A)[aidx4] = o;
    }
}

// ---------------- main GEMM: 64x64 warp tiles, occ 1, 4-stage ring ----------------
#define BM 128
#define BN 256
#define BK 64
#define KT (KDIM / BK)                /* 64 iterations */
#define NSTAGE 4
#define ASTR 72                       /* fp16 units; 144B row stride -> conflict-free */
#define BSTR 264                      /* fp16 units; 528B row stride */
#define A_BYTES (BM * ASTR * 2)       /* 18432 */
#define B_BYTES (BK * BSTR * 2)       /* 33792 */
#define OFF_B   A_BYTES
#define STAGE_BYTES (A_BYTES + B_BYTES)  /* 52224 */

__device__ __forceinline__ void cp16(uint32_t dst, const void* src)
{
    asm volatile("cp.async.cg.shared.global [%0], [%1], 16;\n" :: "r"(dst), "l"(src));
}
__device__ __forceinline__ void ldsm4(uint32_t* r, uint32_t addr)
{
    asm volatile("ldmatrix.sync.aligned.m8n8.x4.shared.b16 {%0,%1,%2,%3}, [%4];\n"
                 : "=r"(r[0]), "=r"(r[1]), "=r"(r[2]), "=r"(r[3]) : "r"(addr));
}
__device__ __forceinline__ void ldsm4t(uint32_t* r, uint32_t addr)
{
    asm volatile("ldmatrix.sync.aligned.m8n8.x4.trans.shared.b16 {%0,%1,%2,%3}, [%4];\n"
                 : "=r"(r[0]), "=r"(r[1]), "=r"(r[2]), "=r"(r[3]) : "r"(addr));
}
__device__ __forceinline__ void mma16816(float* d, const uint32_t* a, const uint32_t* b)
{
    asm volatile("mma.sync.aligned.m16n8k16.row.col.f32.f16.f16.f32 "
                 "{%0,%1,%2,%3},{%4,%5,%6,%7},{%8,%9},{%0,%1,%2,%3};\n"
                 : "+f"(d[0]), "+f"(d[1]), "+f"(d[2]), "+f"(d[3])
                 : "r"(a[0]), "r"(a[1]), "r"(a[2]), "r"(a[3]), "r"(b[0]), "r"(b[1]));
}

__global__ void __launch_bounds__(256, 1)
gemm_kernel(float* __restrict__ out, const float* __restrict__ b_enc)
{
    extern __shared__ char smem[];
    const int tid = threadIdx.x;
    const int warp = tid >> 5, lane = tid & 31;
    const int n0 = blockIdx.x * BN;
    const int m0 = blockIdx.y * BM;
    const int wm = warp & 1, wn = warp >> 1;   // 2 (M) x 4 (N) warps; warp tile 64x64

    const uint32_t sbase = (uint32_t)__cvta_generic_to_shared(smem);

    float d[4][8][4];
#pragma unroll
    for (int mt = 0; mt < 4; mt++)
#pragma unroll
        for (int nt = 0; nt < 8; nt++)
#pragma unroll
            for (int i = 0; i < 4; i++) d[mt][nt][i] = 0.0f;

    // one 16B chunk-group (256 threads wide) of a stage; groups 0-3 = A, 4-11 = B
    auto loadSlice = [&](uint32_t st, int bk, int g) {
        if (g < 4) {
            const int idx = g * 256 + tid;
            const int r = idx >> 3, c = idx & 7;
            cp16(st + (uint32_t)(r * ASTR + c * 8) * 2,
                 g_A + (size_t)(m0 + r) * KDIM + bk + c * 8);
        } else {
            const int idx = (g - 4) * 256 + tid;
            const int r = idx >> 5, c = idx & 31;
            cp16(st + OFF_B + (uint32_t)(r * BSTR + c * 8) * 2,
                 g_W + (size_t)(bk + r) * HDIM + n0 + c * 8);
        }
    };
    auto loadStage = [&](int s, int kt) {
        const uint32_t st = sbase + (uint32_t)s * STAGE_BYTES;
#pragma unroll
        for (int g = 0; g < 12; g++) loadSlice(st, kt * BK, g);
        asm volatile("cp.async.commit_group;\n");
    };

    uint32_t af[2][4][4], bf[2][4][4];
    auto loadFrags = [&](uint32_t st, int ks, int buf) {
#pragma unroll
        for (int mt = 0; mt < 4; mt++) {
            const int r = wm * 64 + mt * 16 + (lane & 15);
            const int c = ks * 16 + (lane >> 4) * 8;
            ldsm4(af[buf][mt], st + (uint32_t)(r * ASTR + c) * 2);
        }
        const int part = lane >> 3;
        const int kr = ks * 16 + (part & 1) * 8 + (lane & 7);
#pragma unroll
        for (int g = 0; g < 4; g++) {
            const int ncol = wn * 64 + g * 16 + (part >> 1) * 8;
            ldsm4t(bf[buf][g], st + OFF_B + (uint32_t)(kr * BSTR + ncol) * 2);
        }
    };

    loadStage(0, 0);
    loadStage(1, 1);
    loadStage(2, 2);

    for (int kt = 0; kt < KT; kt++) {
        if      (kt < KT - 2) asm volatile("cp.async.wait_group 2;\n");
        else if (kt < KT - 1) asm volatile("cp.async.wait_group 1;\n");
        else                  asm volatile("cp.async.wait_group 0;\n");
        __syncthreads();

        const uint32_t st = sbase + (uint32_t)(kt & (NSTAGE - 1)) * STAGE_BYTES;
        loadFrags(st, 0, 0);

        const bool pf = (kt + 3 < KT);
        const uint32_t pst = sbase + (uint32_t)((kt + 3) & (NSTAGE - 1)) * STAGE_BYTES;
        const int pbk = (kt + 3) * BK;

#pragma unroll
        for (int ks = 0; ks < 4; ks++) {
            if (ks < 3) loadFrags(st, ks + 1, (ks + 1) & 1);
            if (pf) {               // spread prefetch: 3 chunk-groups per ks
                loadSlice(pst, pbk, 3 * ks + 0);
                loadSlice(pst, pbk, 3 * ks + 1);
                loadSlice(pst, pbk, 3 * ks + 2);
            }
            const int cur = ks & 1;
#pragma unroll
            for (int mt = 0; mt < 4; mt++)
#pragma unroll
                for (int g = 0; g < 4; g++)
#pragma unroll
                    for (int h = 0; h < 2; h++)
                        mma16816(d[mt][g * 2 + h], af[cur][mt], &bf[cur][g][h * 2]);
        }
        if (pf) asm volatile("cp.async.commit_group;\n");
    }

    // epilogue: + sum_k c[b,k]*b_enc[k,h]
#pragma unroll
    for (int mt = 0; mt < 4; mt++) {
        const int rbase = m0 + wm * 64 + mt * 16 + (lane >> 2);
#pragma unroll
        for (int half = 0; half < 2; half++) {
            const int r = rbase + half * 8;
            const float4 c4 = *reinterpret_cast<const float4*>(&g_c[r * KMOD]);
#pragma unroll
            for (int nt = 0; nt < 8; nt++) {
                const int c = n0 + wn * 64 + nt * 8 + (lane & 3) * 2;
                const float bias0 = c4.x * b_enc[0 * HDIM + c]     + c4.y * b_enc[1 * HDIM + c]
                                  + c4.z * b_enc[2 * HDIM + c]     + c4.w * b_enc[3 * HDIM + c];
                const float bias1 = c4.x * b_enc[0 * HDIM + c + 1] + c4.y * b_enc[1 * HDIM + c + 1]
                                  + c4.z * b_enc[2 * HDIM + c + 1] + c4.w * b_enc[3 * HDIM + c + 1];
                float2 o;
                o.x = d[mt][nt][half * 2 + 0] + bias0;
                o.y = d[mt][nt][half * 2 + 1] + bias1;
                *reinterpret_cast<float2*>(out + (size_t)r * HDIM + c) = o;
            }
        }
    }
}

// ---------------- launch ----------------
extern "C" void kernel_launch(void* const* d_in, const int* in_sizes, int n_in,
                              void* d_out, int out_size)
{
    const float* context  = (const float*)d_in[0];
    const float* x        = (const float*)d_in[1];
    const float* gumbel   = (const float*)d_in[2];
    const float* W1       = (const float*)d_in[3];
    const float* b1       = (const float*)d_in[4];
    const float* gln      = (const float*)d_in[5];
    const float* bln      = (const float*)d_in[6];
    const float* W2       = (const float*)d_in[7];
    const float* b2       = (const float*)d_in[8];
    const float* W3       = (const float*)d_in[9];
    const float* b3       = (const float*)d_in[10];
    const float* prior    = (const float*)d_in[11];
    const float* W_enc    = (const float*)d_in[12];
    const float* b_enc    = (const float*)d_in[13];
    const float* fusion_w = (const float*)d_in[14];
    float* out = (float*)d_out;

    cudaFuncSetAttribute(router_kernel, cudaFuncAttributeMaxDynamicSharedMemorySize,
                         ROUTER_SMEM);
    router_kernel<<<BDIM / RROWS, 256, ROUTER_SMEM>>>(context, gumbel, W1, b1, gln, bln,
                                                      W2, b2, W3, b3, prior, fusion_w,
                                                      W_enc);
    conv_a_kernel<<<2048, 256>>>(x);

    const int dyn = NSTAGE * STAGE_BYTES;   // 208896
    cudaFuncSetAttribute(gemm_kernel, cudaFuncAttributeMaxDynamicSharedMemorySize, dyn);
    gemm_kernel<<<dim3(HDIM / BN, BDIM / BM), 256, dyn>>>(out, b_enc);
}

// round 7
// speedup vs baseline: 2.8242x; 1.0377x over previous
#include <cuda_runtime.h>
#include <cuda_fp16.h>
#include <cstdint>

#define BDIM 4096
#define KMOD 4
#define DIN  1024
#define HDIM 1024
#define CTXD 256
#define RHD  64
#define KDIM 4096  /* KMOD*DIN : concatenated reduction dim */

// ---------------- scratch (device globals: no runtime allocation) ----------------
__device__ float   g_c[BDIM * KMOD];                  // gate coeff c[b,k]
__device__ __half  g_A[(size_t)BDIM * KDIM];          // fp16(c*x)   [B][K]
__device__ __half  g_W[(size_t)KDIM * HDIM];          // fp16(W_enc) [K][H]

// ---------------- router: pure MLP, weights cached in smem ----------------
#define RROWS 16
__global__ void router_kernel(const float* __restrict__ context,
                              const float* __restrict__ gumbel,
                              const float* __restrict__ W1, const float* __restrict__ b1,
                              const float* __restrict__ gln, const float* __restrict__ bln,
                              const float* __restrict__ W2, const float* __restrict__ b2,
                              const float* __restrict__ W3, const float* __restrict__ b3,
                              const float* __restrict__ prior,
                              const float* __restrict__ fusion_w)
{
    extern __shared__ float rs[];
    float* w1_s  = rs;                       // 16384
    float* w2_s  = w1_s + CTXD * RHD;        // 2048
    float* w3_s  = w2_s + RHD * (RHD / 2);   // 128
    float* ctx_s = w3_s + (RHD / 2) * KMOD;  // 4096
    float* h1_s  = ctx_s + RROWS * CTXD;     // 1024
    float* h2_s  = h1_s + RROWS * RHD;       // 512

    const int tid = threadIdx.x;
    const int warp = tid >> 5, lane = tid & 31;
    const int b0 = blockIdx.x * RROWS;

    for (int i = tid; i < CTXD * RHD / 4; i += 256)
        reinterpret_cast<float4*>(w1_s)[i] = reinterpret_cast<const float4*>(W1)[i];
    for (int i = tid; i < RHD * (RHD / 2) / 4; i += 256)
        reinterpret_cast<float4*>(w2_s)[i] = reinterpret_cast<const float4*>(W2)[i];
    if (tid < (RHD / 2) * KMOD / 4)
        reinterpret_cast<float4*>(w3_s)[tid] = reinterpret_cast<const float4*>(W3)[tid];
    for (int i = tid; i < RROWS * CTXD / 4; i += 256)
        reinterpret_cast<float4*>(ctx_s)[i] =
            reinterpret_cast<const float4*>(context + (size_t)b0 * CTXD)[i];
    __syncthreads();

#pragma unroll
    for (int rr = 0; rr < 2; rr++) {
        const int row = warp + rr * 8;         // local row, 8 warps x 2 passes
        const float* crow = ctx_s + row * CTXD;

        float h[2];
#pragma unroll
        for (int jj = 0; jj < 2; jj++) {
            const int j = lane + jj * 32;
            float acc = b1[j];
            for (int i = 0; i < CTXD; i++) acc = fmaf(crow[i], w1_s[i * RHD + j], acc);
            h[jj] = acc;
        }
        float s  = h[0] + h[1];
        float sq = h[0] * h[0] + h[1] * h[1];
#pragma unroll
        for (int o = 16; o; o >>= 1) {
            s  += __shfl_xor_sync(0xffffffffu, s,  o);
            sq += __shfl_xor_sync(0xffffffffu, sq, o);
        }
        const float mu   = s * (1.0f / RHD);
        const float var  = sq * (1.0f / RHD) - mu * mu;
        const float rstd = rsqrtf(var + 1e-5f);
#pragma unroll
        for (int jj = 0; jj < 2; jj++) {
            const int j = lane + jj * 32;
            const float v = (h[jj] - mu) * rstd * gln[j] + bln[j];
            h1_s[row * RHD + j] = fmaxf(v, 0.0f);
        }
        __syncwarp();
        float acc2 = b2[lane];
        for (int i = 0; i < RHD; i++)
            acc2 = fmaf(h1_s[row * RHD + i], w2_s[i * (RHD / 2) + lane], acc2);
        h2_s[row * (RHD / 2) + lane] = fmaxf(acc2, 0.0f);
        __syncwarp();

        float logit = 0.0f;
        if (lane < KMOD) {
            logit = b3[lane] + prior[lane];
            for (int i = 0; i < RHD / 2; i++)
                logit = fmaf(h2_s[row * (RHD / 2) + i], w3_s[i * KMOD + lane], logit);
        }
        float lg[4];
#pragma unroll
        for (int k = 0; k < 4; k++) lg[k] = __shfl_sync(0xffffffffu, logit, k);

        if (lane == 0) {
            const int b = b0 + row;
            float fw[4], m = -1e30f;
#pragma unroll
            for (int k = 0; k < 4; k++) { fw[k] = fusion_w[k]; m = fmaxf(m, fw[k]); }
            float se = 0.0f;
#pragma unroll
            for (int k = 0; k < 4; k++) { fw[k] = expf(fw[k] - m); se += fw[k]; }
            const float inv = 1.0f / se;
            int i1 = 0;
#pragma unroll
            for (int k = 1; k < 4; k++) if (lg[k] > lg[i1]) i1 = k;
            int i2 = (i1 == 0) ? 1 : 0;
#pragma unroll
            for (int k = 0; k < 4; k++) if (k != i1 && lg[k] > lg[i2]) i2 = k;
#pragma unroll
            for (int k = 0; k < 4; k++) {
                const float soft = 1.0f / (1.0f + expf(-(lg[k] + gumbel[b * KMOD + k])));
                const float mask = (k == i1 || k == i2) ? fmaxf(soft, 1.0f) : soft;
                const float cc   = (mask > 0.5f) ? (fw[k] * inv) * mask : 0.0f;
                g_c[b * KMOD + k] = cc;
            }
        }
    }
}
#define ROUTER_SMEM ((CTXD * RHD + RHD * (RHD / 2) + (RHD / 2) * KMOD \
                      + RROWS * CTXD + RROWS * RHD + RROWS * (RHD / 2)) * 4)

// ---------------- combined fp16 conversion: W_enc -> g_W, c*x -> g_A ----------------
#define W4 (KDIM * HDIM / 4)          /* 1048576 float4 units */
#define A4 (KMOD * BDIM * (DIN / 4))  /* 4194304 float4 units */
__global__ void conv_kernel(const float* __restrict__ x, const float* __restrict__ W_enc)
{
    const int stride = gridDim.x * blockDim.x;
    for (int t = blockIdx.x * blockDim.x + threadIdx.x; t < W4 + A4; t += stride) {
        if (t < W4) {
            const float4 v = reinterpret_cast<const float4*>(W_enc)[t];
            __half2 p0 = __halves2half2(__float2half_rn(v.x), __float2half_rn(v.y));
            __half2 p1 = __halves2half2(__float2half_rn(v.z), __float2half_rn(v.w));
            uint2 o;
            o.x = *reinterpret_cast<uint32_t*>(&p0);
            o.y = *reinterpret_cast<uint32_t*>(&p1);
            reinterpret_cast<uint2*>(g_W)[t] = o;
        } else {
            const int ta = t - W4;
            const int d4  = ta & (DIN / 4 - 1);
            const int rem = ta >> 8;
            const int b   = rem & (BDIM - 1);
            const int mod = rem >> 12;
            const float cc = g_c[b * KMOD + mod];
            const float4 v = reinterpret_cast<const float4*>(x)[ta];
            __half2 p0 = __halves2half2(__float2half_rn(v.x * cc), __float2half_rn(v.y * cc));
            __half2 p1 = __halves2half2(__float2half_rn(v.z * cc), __float2half_rn(v.w * cc));
            uint2 o;
            o.x = *reinterpret_cast<uint32_t*>(&p0);
            o.y = *reinterpret_cast<uint32_t*>(&p1);
            const size_t aidx4 = ((size_t)b * KDIM + (size_t)mod * DIN) / 4 + d4;
            reinterpret_cast<uint2*>(g_A)[aidx4] = o;
        }
    }
}

// ---------------- main GEMM: 64x64 warp tiles, occ 1, 4-stage ring ----------------
#define BM 128
#define BN 256
#define BK 64
#define KT (KDIM / BK)                /* 64 iterations */
#define NSTAGE 4
#define ASTR 72                       /* fp16 units; 144B row stride -> conflict-free */
#define BSTR 264                      /* fp16 units; 528B row stride */
#define A_BYTES (BM * ASTR * 2)       /* 18432 */
#define B_BYTES (BK * BSTR * 2)       /* 33792 */
#define OFF_B   A_BYTES
#define STAGE_BYTES (A_BYTES + B_BYTES)  /* 52224 */

__device__ __forceinline__ void cp16(uint32_t dst, const void* src)
{
    asm volatile("cp.async.cg.shared.global [%0], [%1], 16;\n" :: "r"(dst), "l"(src));
}
__device__ __forceinline__ void ldsm4(uint32_t* r, uint32_t addr)
{
    asm volatile("ldmatrix.sync.aligned.m8n8.x4.shared.b16 {%0,%1,%2,%3}, [%4];\n"
                 : "=r"(r[0]), "=r"(r[1]), "=r"(r[2]), "=r"(r[3]) : "r"(addr));
}
__device__ __forceinline__ void ldsm4t(uint32_t* r, uint32_t addr)
{
    asm volatile("ldmatrix.sync.aligned.m8n8.x4.trans.shared.b16 {%0,%1,%2,%3}, [%4];\n"
                 : "=r"(r[0]), "=r"(r[1]), "=r"(r[2]), "=r"(r[3]) : "r"(addr));
}
__device__ __forceinline__ void mma16816(float* d, const uint32_t* a, const uint32_t* b)
{
    asm volatile("mma.sync.aligned.m16n8k16.row.col.f32.f16.f16.f32 "
                 "{%0,%1,%2,%3},{%4,%5,%6,%7},{%8,%9},{%0,%1,%2,%3};\n"
                 : "+f"(d[0]), "+f"(d[1]), "+f"(d[2]), "+f"(d[3])
                 : "r"(a[0]), "r"(a[1]), "r"(a[2]), "r"(a[3]), "r"(b[0]), "r"(b[1]));
}

__global__ void __launch_bounds__(256, 1)
gemm_kernel(float* __restrict__ out, const float* __restrict__ b_enc)
{
    extern __shared__ char smem[];
    const int tid = threadIdx.x;
    const int warp = tid >> 5, lane = tid & 31;
    const int n0 = blockIdx.x * BN;
    const int m0 = blockIdx.y * BM;
    const int wm = warp & 1, wn = warp >> 1;   // 2 (M) x 4 (N) warps; warp tile 64x64

    const uint32_t sbase = (uint32_t)__cvta_generic_to_shared(smem);

    float d[4][8][4];
#pragma unroll
    for (int mt = 0; mt < 4; mt++)
#pragma unroll
        for (int nt = 0; nt < 8; nt++)
#pragma unroll
            for (int i = 0; i < 4; i++) d[mt][nt][i] = 0.0f;

    // one 16B chunk-group (256 threads wide) of a stage; groups 0-3 = A, 4-11 = B
    auto loadSlice = [&](uint32_t st, int bk, int g) {
        if (g < 4) {
            const int idx = g * 256 + tid;
            const int r = idx >> 3, c = idx & 7;
            cp16(st + (uint32_t)(r * ASTR + c * 8) * 2,
                 g_A + (size_t)(m0 + r) * KDIM + bk + c * 8);
        } else {
            const int idx = (g - 4) * 256 + tid;
            const int r = idx >> 5, c = idx & 31;
            cp16(st + OFF_B + (uint32_t)(r * BSTR + c * 8) * 2,
                 g_W + (size_t)(bk + r) * HDIM + n0 + c * 8);
        }
    };
    auto loadStage = [&](int s, int kt) {
        const uint32_t st = sbase + (uint32_t)s * STAGE_BYTES;
#pragma unroll
        for (int g = 0; g < 12; g++) loadSlice(st, kt * BK, g);
        asm volatile("cp.async.commit_group;\n");
    };

    uint32_t af[2][4][4], bf[2][4][4];
    auto loadFrags = [&](uint32_t st, int ks, int buf) {
#pragma unroll
        for (int mt = 0; mt < 4; mt++) {
            const int r = wm * 64 + mt * 16 + (lane & 15);
            const int c = ks * 16 + (lane >> 4) * 8;
            ldsm4(af[buf][mt], st + (uint32_t)(r * ASTR + c) * 2);
        }
        const int part = lane >> 3;
        const int kr = ks * 16 + (part & 1) * 8 + (lane & 7);
#pragma unroll
        for (int g = 0; g < 4; g++) {
            const int ncol = wn * 64 + g * 16 + (part >> 1) * 8;
            ldsm4t(bf[buf][g], st + OFF_B + (uint32_t)(kr * BSTR + ncol) * 2);
        }
    };

    loadStage(0, 0);
    loadStage(1, 1);
    loadStage(2, 2);

    for (int kt = 0; kt < KT; kt++) {
        if      (kt < KT - 2) asm volatile("cp.async.wait_group 2;\n");
        else if (kt < KT - 1) asm volatile("cp.async.wait_group 1;\n");
        else                  asm volatile("cp.async.wait_group 0;\n");
        __syncthreads();

        const uint32_t st = sbase + (uint32_t)(kt & (NSTAGE - 1)) * STAGE_BYTES;
        loadFrags(st, 0, 0);

        const bool pf = (kt + 3 < KT);
        const uint32_t pst = sbase + (uint32_t)((kt + 3) & (NSTAGE - 1)) * STAGE_BYTES;
        const int pbk = (kt + 3) * BK;

#pragma unroll
        for (int ks = 0; ks < 4; ks++) {
            if (ks < 3) loadFrags(st, ks + 1, (ks + 1) & 1);
            if (pf) {               // spread prefetch: 3 chunk-groups per ks
                loadSlice(pst, pbk, 3 * ks + 0);
                loadSlice(pst, pbk, 3 * ks + 1);
                loadSlice(pst, pbk, 3 * ks + 2);
            }
            const int cur = ks & 1;
#pragma unroll
            for (int mt = 0; mt < 4; mt++)
#pragma unroll
                for (int g = 0; g < 4; g++)
#pragma unroll
                    for (int h = 0; h < 2; h++)
                        mma16816(d[mt][g * 2 + h], af[cur][mt], &bf[cur][g][h * 2]);
        }
        if (pf) asm volatile("cp.async.commit_group;\n");
    }

    // epilogue: + sum_k c[b,k]*b_enc[k,h]
#pragma unroll
    for (int mt = 0; mt < 4; mt++) {
        const int rbase = m0 + wm * 64 + mt * 16 + (lane >> 2);
#pragma unroll
        for (int half = 0; half < 2; half++) {
            const int r = rbase + half * 8;
            const float4 c4 = *reinterpret_cast<const float4*>(&g_c[r * KMOD]);
#pragma unroll
            for (int nt = 0; nt < 8; nt++) {
                const int c = n0 + wn * 64 + nt * 8 + (lane & 3) * 2;
                const float bias0 = c4.x * b_enc[0 * HDIM + c]     + c4.y * b_enc[1 * HDIM + c]
                                  + c4.z * b_enc[2 * HDIM + c]     + c4.w * b_enc[3 * HDIM + c];
                const float bias1 = c4.x * b_enc[0 * HDIM + c + 1] + c4.y * b_enc[1 * HDIM + c + 1]
                                  + c4.z * b_enc[2 * HDIM + c + 1] + c4.w * b_enc[3 * HDIM + c + 1];
                float2 o;
                o.x = d[mt][nt][half * 2 + 0] + bias0;
                o.y = d[mt][nt][half * 2 + 1] + bias1;
                *reinterpret_cast<float2*>(out + (size_t)r * HDIM + c) = o;
            }
        }
    }
}

// ---------------- launch ----------------
extern "C" void kernel_launch(void* const* d_in, const int* in_sizes, int n_in,
                              void* d_out, int out_size)
{
    const float* context  = (const float*)d_in[0];
    const float* x        = (const float*)d_in[1];
    const float* gumbel   = (const float*)d_in[2];
    const float* W1       = (const float*)d_in[3];
    const float* b1       = (const float*)d_in[4];
    const float* gln      = (const float*)d_in[5];
    const float* bln      = (const float*)d_in[6];
    const float* W2       = (const float*)d_in[7];
    const float* b2       = (const float*)d_in[8];
    const float* W3       = (const float*)d_in[9];
    const float* b3       = (const float*)d_in[10];
    const float* prior    = (const float*)d_in[11];
    const float* W_enc    = (const float*)d_in[12];
    const float* b_enc    = (const float*)d_in[13];
    const float* fusion_w = (const float*)d_in[14];
    float* out = (float*)d_out;

    cudaFuncSetAttribute(router_kernel, cudaFuncAttributeMaxDynamicSharedMemorySize,
                         ROUTER_SMEM);
    router_kernel<<<BDIM / RROWS, 256, ROUTER_SMEM>>>(context, gumbel, W1, b1, gln, bln,
                                                      W2, b2, W3, b3, prior, fusion_w);
    conv_kernel<<<2368, 256>>>(x, W_enc);   // 16 blocks x 148 SMs

    const int dyn = NSTAGE * STAGE_BYTES;   // 208896
    cudaFuncSetAttribute(gemm_kernel, cudaFuncAttributeMaxDynamicSharedMemorySize, dyn);
    gemm_kernel<<<dim3(HDIM / BN, BDIM / BM), 256, dyn>>>(out, b_enc);
}

// round 8
// speedup vs baseline: 2.9528x; 1.0455x over previous
#include <cuda_runtime.h>
#include <cuda_fp16.h>
#include <cstdint>

#define BDIM 4096
#define KMOD 4
#define DIN  1024
#define HDIM 1024
#define CTXD 256
#define RHD  64
#define KDIM 4096  /* KMOD*DIN : concatenated reduction dim */

// ---------------- scratch (device globals: no runtime allocation) ----------------
__device__ float   g_c[BDIM * KMOD];                  // gate coeff c[b,k]
__device__ __half  g_A[(size_t)BDIM * KDIM];          // fp16(c*x)   [B][K]
__device__ __half  g_W[(size_t)KDIM * HDIM];          // fp16(W_enc) [K][H]

// ---------------- router: 2 rows/warp, 8 independent FMA chains/thread ----------------
#define RROWS 16
__global__ void router_kernel(const float* __restrict__ context,
                              const float* __restrict__ gumbel,
                              const float* __restrict__ W1, const float* __restrict__ b1,
                              const float* __restrict__ gln, const float* __restrict__ bln,
                              const float* __restrict__ W2, const float* __restrict__ b2,
                              const float* __restrict__ W3, const float* __restrict__ b3,
                              const float* __restrict__ prior,
                              const float* __restrict__ fusion_w)
{
    extern __shared__ float rs[];
    float* w1_s  = rs;                       // 16384 floats? (CTXD*RHD)
    float* w2_s  = w1_s + CTXD * RHD;
    float* w3_s  = w2_s + RHD * (RHD / 2);
    float* ctx_s = w3_s + (RHD / 2) * KMOD;
    float* h1_s  = ctx_s + RROWS * CTXD;
    float* h2_s  = h1_s + RROWS * RHD;

    const int tid = threadIdx.x;
    const int warp = tid >> 5, lane = tid & 31;
    const int b0 = blockIdx.x * RROWS;

    for (int i = tid; i < CTXD * RHD / 4; i += 256)
        reinterpret_cast<float4*>(w1_s)[i] = reinterpret_cast<const float4*>(W1)[i];
    for (int i = tid; i < RHD * (RHD / 2) / 4; i += 256)
        reinterpret_cast<float4*>(w2_s)[i] = reinterpret_cast<const float4*>(W2)[i];
    if (tid < (RHD / 2) * KMOD / 4)
        reinterpret_cast<float4*>(w3_s)[tid] = reinterpret_cast<const float4*>(W3)[tid];
    for (int i = tid; i < RROWS * CTXD / 4; i += 256)
        reinterpret_cast<float4*>(ctx_s)[i] =
            reinterpret_cast<const float4*>(context + (size_t)b0 * CTXD)[i];
    __syncthreads();

    // each warp owns 2 rows
    const int r0 = warp * 2, r1 = warp * 2 + 1;
    const float* c0 = ctx_s + r0 * CTXD;
    const float* c1 = ctx_s + r1 * CTXD;

    // ---- layer 1: 8 independent chains [row][jj][phase] ----
    float acc[2][2][2];
#pragma unroll
    for (int a = 0; a < 2; a++)
#pragma unroll
        for (int b = 0; b < 2; b++)
#pragma unroll
            for (int p = 0; p < 2; p++) acc[a][b][p] = 0.0f;

#pragma unroll 4
    for (int i = 0; i < CTXD; i += 2) {
#pragma unroll
        for (int p = 0; p < 2; p++) {
            const float x0 = c0[i + p];
            const float x1 = c1[i + p];
#pragma unroll
            for (int jj = 0; jj < 2; jj++) {
                const float w = w1_s[(i + p) * RHD + lane + jj * 32];
                acc[0][jj][p] = fmaf(x0, w, acc[0][jj][p]);
                acc[1][jj][p] = fmaf(x1, w, acc[1][jj][p]);
            }
        }
    }

#pragma unroll
    for (int rr = 0; rr < 2; rr++) {
        const int row = (rr == 0) ? r0 : r1;
        float h[2];
#pragma unroll
        for (int jj = 0; jj < 2; jj++)
            h[jj] = acc[rr][jj][0] + acc[rr][jj][1] + b1[lane + jj * 32];

        float s  = h[0] + h[1];
        float sq = h[0] * h[0] + h[1] * h[1];
#pragma unroll
        for (int o = 16; o; o >>= 1) {
            s  += __shfl_xor_sync(0xffffffffu, s,  o);
            sq += __shfl_xor_sync(0xffffffffu, sq, o);
        }
        const float mu   = s * (1.0f / RHD);
        const float var  = sq * (1.0f / RHD) - mu * mu;
        const float rstd = rsqrtf(var + 1e-5f);
#pragma unroll
        for (int jj = 0; jj < 2; jj++) {
            const int j = lane + jj * 32;
            const float v = (h[jj] - mu) * rstd * gln[j] + bln[j];
            h1_s[row * RHD + j] = fmaxf(v, 0.0f);
        }
        __syncwarp();

        // ---- layer 2: 2 partial accumulators ----
        float a2a = 0.0f, a2b = 0.0f;
#pragma unroll 4
        for (int i = 0; i < RHD; i += 2) {
            a2a = fmaf(h1_s[row * RHD + i],     w2_s[i * (RHD / 2) + lane],       a2a);
            a2b = fmaf(h1_s[row * RHD + i + 1], w2_s[(i + 1) * (RHD / 2) + lane], a2b);
        }
        h2_s[row * (RHD / 2) + lane] = fmaxf(a2a + a2b + b2[lane], 0.0f);
        __syncwarp();

        // ---- layer 3 + gate ----
        float logit = 0.0f;
        if (lane < KMOD) {
            logit = b3[lane] + prior[lane];
            for (int i = 0; i < RHD / 2; i++)
                logit = fmaf(h2_s[row * (RHD / 2) + i], w3_s[i * KMOD + lane], logit);
        }
        float lg[4];
#pragma unroll
        for (int k = 0; k < 4; k++) lg[k] = __shfl_sync(0xffffffffu, logit, k);

        if (lane == 0) {
            const int b = b0 + row;
            float fw[4], m = -1e30f;
#pragma unroll
            for (int k = 0; k < 4; k++) { fw[k] = fusion_w[k]; m = fmaxf(m, fw[k]); }
            float se = 0.0f;
#pragma unroll
            for (int k = 0; k < 4; k++) { fw[k] = expf(fw[k] - m); se += fw[k]; }
            const float inv = 1.0f / se;
            int i1 = 0;
#pragma unroll
            for (int k = 1; k < 4; k++) if (lg[k] > lg[i1]) i1 = k;
            int i2 = (i1 == 0) ? 1 : 0;
#pragma unroll
            for (int k = 0; k < 4; k++) if (k != i1 && lg[k] > lg[i2]) i2 = k;
#pragma unroll
            for (int k = 0; k < 4; k++) {
                const float soft = 1.0f / (1.0f + expf(-(lg[k] + gumbel[b * KMOD + k])));
                const float mask = (k == i1 || k == i2) ? fmaxf(soft, 1.0f) : soft;
                const float cc   = (mask > 0.5f) ? (fw[k] * inv) * mask : 0.0f;
                g_c[b * KMOD + k] = cc;
            }
        }
    }
}
#define ROUTER_SMEM ((CTXD * RHD + RHD * (RHD / 2) + (RHD / 2) * KMOD \
                      + RROWS * CTXD + RROWS * RHD + RROWS * (RHD / 2)) * 4)

// ---------------- combined fp16 conversion: W_enc -> g_W, c*x -> g_A ----------------
#define W4 (KDIM * HDIM / 4)          /* 1048576 float4 units */
#define A4 (KMOD * BDIM * (DIN / 4))  /* 4194304 float4 units */
__global__ void conv_kernel(const float* __restrict__ x, const float* __restrict__ W_enc)
{
    const int stride = gridDim.x * blockDim.x;
    for (int t = blockIdx.x * blockDim.x + threadIdx.x; t < W4 + A4; t += stride) {
        if (t < W4) {
            const float4 v = reinterpret_cast<const float4*>(W_enc)[t];
            __half2 p0 = __halves2half2(__float2half_rn(v.x), __float2half_rn(v.y));
            __half2 p1 = __halves2half2(__float2half_rn(v.z), __float2half_rn(v.w));
            uint2 o;
            o.x = *reinterpret_cast<uint32_t*>(&p0);
            o.y = *reinterpret_cast<uint32_t*>(&p1);
            reinterpret_cast<uint2*>(g_W)[t] = o;
        } else {
            const int ta = t - W4;
            const int d4  = ta & (DIN / 4 - 1);
            const int rem = ta >> 8;
            const int b   = rem & (BDIM - 1);
            const int mod = rem >> 12;
            const float cc = g_c[b * KMOD + mod];
            const float4 v = reinterpret_cast<const float4*>(x)[ta];
            __half2 p0 = __halves2half2(__float2half_rn(v.x * cc), __float2half_rn(v.y * cc));
            __half2 p1 = __halves2half2(__float2half_rn(v.z * cc), __float2half_rn(v.w * cc));
            uint2 o;
            o.x = *reinterpret_cast<uint32_t*>(&p0);
            o.y = *reinterpret_cast<uint32_t*>(&p1);
            const size_t aidx4 = ((size_t)b * KDIM + (size_t)mod * DIN) / 4 + d4;
            reinterpret_cast<uint2*>(g_A)[aidx4] = o;
        }
    }
}

// ---------------- main GEMM: 64x64 warp tiles, occ 1, 4-stage ring ----------------
#define BM 128
#define BN 256
#define BK 64
#define KT (KDIM / BK)                /* 64 iterations */
#define NSTAGE 4
#define ASTR 72                       /* fp16 units; 144B row stride -> conflict-free */
#define BSTR 264                      /* fp16 units; 528B row stride */
#define A_BYTES (BM * ASTR * 2)       /* 18432 */
#define B_BYTES (BK * BSTR * 2)       /* 33792 */
#define OFF_B   A_BYTES
#define STAGE_BYTES (A_BYTES + B_BYTES)  /* 52224 */

__device__ __forceinline__ void cp16(uint32_t dst, const void* src)
{
    asm volatile("cp.async.cg.shared.global [%0], [%1], 16;\n" :: "r"(dst), "l"(src));
}
__device__ __forceinline__ void ldsm4(uint32_t* r, uint32_t addr)
{
    asm volatile("ldmatrix.sync.aligned.m8n8.x4.shared.b16 {%0,%1,%2,%3}, [%4];\n"
                 : "=r"(r[0]), "=r"(r[1]), "=r"(r[2]), "=r"(r[3]) : "r"(addr));
}
__device__ __forceinline__ void ldsm4t(uint32_t* r, uint32_t addr)
{
    asm volatile("ldmatrix.sync.aligned.m8n8.x4.trans.shared.b16 {%0,%1,%2,%3}, [%4];\n"
                 : "=r"(r[0]), "=r"(r[1]), "=r"(r[2]), "=r"(r[3]) : "r"(addr));
}
__device__ __forceinline__ void mma16816(float* d, const uint32_t* a, const uint32_t* b)
{
    asm volatile("mma.sync.aligned.m16n8k16.row.col.f32.f16.f16.f32 "
                 "{%0,%1,%2,%3},{%4,%5,%6,%7},{%8,%9},{%0,%1,%2,%3};\n"
                 : "+f"(d[0]), "+f"(d[1]), "+f"(d[2]), "+f"(d[3])
                 : "r"(a[0]), "r"(a[1]), "r"(a[2]), "r"(a[3]), "r"(b[0]), "r"(b[1]));
}

__global__ void __launch_bounds__(256, 1)
gemm_kernel(float* __restrict__ out, const float* __restrict__ b_enc)
{
    extern __shared__ char smem[];
    const int tid = threadIdx.x;
    const int warp = tid >> 5, lane = tid & 31;
    const int n0 = blockIdx.x * BN;
    const int m0 = blockIdx.y * BM;
    const int wm = warp & 1, wn = warp >> 1;   // 2 (M) x 4 (N) warps; warp tile 64x64

    const uint32_t sbase = (uint32_t)__cvta_generic_to_shared(smem);

    float d[4][8][4];
#pragma unroll
    for (int mt = 0; mt < 4; mt++)
#pragma unroll
        for (int nt = 0; nt < 8; nt++)
#pragma unroll
            for (int i = 0; i < 4; i++) d[mt][nt][i] = 0.0f;

    // one 16B chunk-group (256 threads wide) of a stage; groups 0-3 = A, 4-11 = B
    auto loadSlice = [&](uint32_t st, int bk, int g) {
        if (g < 4) {
            const int idx = g * 256 + tid;
            const int r = idx >> 3, c = idx & 7;
            cp16(st + (uint32_t)(r * ASTR + c * 8) * 2,
                 g_A + (size_t)(m0 + r) * KDIM + bk + c * 8);
        } else {
            const int idx = (g - 4) * 256 + tid;
            const int r = idx >> 5, c = idx & 31;
            cp16(st + OFF_B + (uint32_t)(r * BSTR + c * 8) * 2,
                 g_W + (size_t)(bk + r) * HDIM + n0 + c * 8);
        }
    };
    auto loadStage = [&](int s, int kt) {
        const uint32_t st = sbase + (uint32_t)s * STAGE_BYTES;
#pragma unroll
        for (int g = 0; g < 12; g++) loadSlice(st, kt * BK, g);
        asm volatile("cp.async.commit_group;\n");
    };

    uint32_t af[2][4][4], bf[2][4][4];
    auto loadFrags = [&](uint32_t st, int ks, int buf) {
#pragma unroll
        for (int mt = 0; mt < 4; mt++) {
            const int r = wm * 64 + mt * 16 + (lane & 15);
            const int c = ks * 16 + (lane >> 4) * 8;
            ldsm4(af[buf][mt], st + (uint32_t)(r * ASTR + c) * 2);
        }
        const int part = lane >> 3;
        const int kr = ks * 16 + (part & 1) * 8 + (lane & 7);
#pragma unroll
        for (int g = 0; g < 4; g++) {
            const int ncol = wn * 64 + g * 16 + (part >> 1) * 8;
            ldsm4t(bf[buf][g], st + OFF_B + (uint32_t)(kr * BSTR + ncol) * 2);
        }
    };

    loadStage(0, 0);
    loadStage(1, 1);
    loadStage(2, 2);

    for (int kt = 0; kt < KT; kt++) {
        if      (kt < KT - 2) asm volatile("cp.async.wait_group 2;\n");
        else if (kt < KT - 1) asm volatile("cp.async.wait_group 1;\n");
        else                  asm volatile("cp.async.wait_group 0;\n");
        __syncthreads();

        const uint32_t st = sbase + (uint32_t)(kt & (NSTAGE - 1)) * STAGE_BYTES;
        loadFrags(st, 0, 0);

        const bool pf = (kt + 3 < KT);
        const uint32_t pst = sbase + (uint32_t)((kt + 3) & (NSTAGE - 1)) * STAGE_BYTES;
        const int pbk = (kt + 3) * BK;

#pragma unroll
        for (int ks = 0; ks < 4; ks++) {
            if (ks < 3) loadFrags(st, ks + 1, (ks + 1) & 1);
            if (pf) {               // spread prefetch: 3 chunk-groups per ks
                loadSlice(pst, pbk, 3 * ks + 0);
                loadSlice(pst, pbk, 3 * ks + 1);
                loadSlice(pst, pbk, 3 * ks + 2);
            }
            const int cur = ks & 1;
#pragma unroll
            for (int mt = 0; mt < 4; mt++)
#pragma unroll
                for (int g = 0; g < 4; g++)
#pragma unroll
                    for (int h = 0; h < 2; h++)
                        mma16816(d[mt][g * 2 + h], af[cur][mt], &bf[cur][g][h * 2]);
        }
        if (pf) asm volatile("cp.async.commit_group;\n");
    }

    // epilogue: + sum_k c[b,k]*b_enc[k,h]
#pragma unroll
    for (int mt = 0; mt < 4; mt++) {
        const int rbase = m0 + wm * 64 + mt * 16 + (lane >> 2);
#pragma unroll
        for (int half = 0; half < 2; half++) {
            const int r = rbase + half * 8;
            const float4 c4 = *reinterpret_cast<const float4*>(&g_c[r * KMOD]);
#pragma unroll
            for (int nt = 0; nt < 8; nt++) {
                const int c = n0 + wn * 64 + nt * 8 + (lane & 3) * 2;
                const float bias0 = c4.x * b_enc[0 * HDIM + c]     + c4.y * b_enc[1 * HDIM + c]
                                  + c4.z * b_enc[2 * HDIM + c]     + c4.w * b_enc[3 * HDIM + c];
                const float bias1 = c4.x * b_enc[0 * HDIM + c + 1] + c4.y * b_enc[1 * HDIM + c + 1]
                                  + c4.z * b_enc[2 * HDIM + c + 1] + c4.w * b_enc[3 * HDIM + c + 1];
                float2 o;
                o.x = d[mt][nt][half * 2 + 0] + bias0;
                o.y = d[mt][nt][half * 2 + 1] + bias1;
                *reinterpret_cast<float2*>(out + (size_t)r * HDIM + c) = o;
            }
        }
    }
}

// ---------------- launch ----------------
extern "C" void kernel_launch(void* const* d_in, const int* in_sizes, int n_in,
                              void* d_out, int out_size)
{
    const float* context  = (const float*)d_in[0];
    const float* x        = (const float*)d_in[1];
    const float* gumbel   = (const float*)d_in[2];
    const float* W1       = (const float*)d_in[3];
    const float* b1       = (const float*)d_in[4];
    const float* gln      = (const float*)d_in[5];
    const float* bln      = (const float*)d_in[6];
    const float* W2       = (const float*)d_in[7];
    const float* b2       = (const float*)d_in[8];
    const float* W3       = (const float*)d_in[9];
    const float* b3       = (const float*)d_in[10];
    const float* prior    = (const float*)d_in[11];
    const float* W_enc    = (const float*)d_in[12];
    const float* b_enc    = (const float*)d_in[13];
    const float* fusion_w = (const float*)d_in[14];
    float* out = (float*)d_out;

    cudaFuncSetAttribute(router_kernel, cudaFuncAttributeMaxDynamicSharedMemorySize,
                         ROUTER_SMEM);
    router_kernel<<<BDIM / RROWS, 256, ROUTER_SMEM>>>(context, gumbel, W1, b1, gln, bln,
                                                      W2, b2, W3, b3, prior, fusion_w);
    conv_kernel<<<2368, 256>>>(x, W_enc);   // 16 blocks x 148 SMs

    const int dyn = NSTAGE * STAGE_BYTES;   // 208896
    cudaFuncSetAttribute(gemm_kernel, cudaFuncAttributeMaxDynamicSharedMemorySize, dyn);
    gemm_kernel<<<dim3(HDIM / BN, BDIM / BM), 256, dyn>>>(out, b_enc);
}